// round 1
// baseline (speedup 1.0000x reference)
#include <cuda_runtime.h>
#include <math.h>

#define BATCH 8
#define SEQ   1024
#define CH    1024
#define HEADS 16
#define HDIM  64
#define RANK  8
#define M_TOT (BATCH*SEQ)   // 8192
#define LORA_SCALE 2.0f

// ---------------- scratch (device globals; no runtime allocation) ----------
__device__ float g_q[BATCH*HEADS*SEQ*HDIM];   // [B,H,N,D]
__device__ float g_k[BATCH*HEADS*SEQ*HDIM];
__device__ float g_v[BATCH*HEADS*SEQ*HDIM];
__device__ float g_ctx[(size_t)M_TOT*CH];     // attention output, [B,N,C]
__device__ float g_xaq[M_TOT*RANK];           // x @ lora_q_a^T
__device__ float g_xav[M_TOT*RANK];           // x @ lora_v_a^T

// ---------------- kernel 1: rank-8 LoRA "A" projections ---------------------
// one block per x-row; 16 groups of 16 threads -> 16 outputs (8 q + 8 v)
__global__ __launch_bounds__(256)
void lora_xa_kernel(const float* __restrict__ x,
                    const float* __restrict__ aq,
                    const float* __restrict__ av)
{
    __shared__ float xs[CH];
    int m = blockIdx.x;
    const float* xr = x + (size_t)m*CH;
    for (int c = threadIdx.x; c < CH; c += 256) xs[c] = xr[c];
    __syncthreads();

    int g = threadIdx.x >> 4;     // 0..15 (output index)
    int l = threadIdx.x & 15;     // lane within group
    const float* arow = (g < 8) ? (aq + g*CH) : (av + (g-8)*CH);
    float p = 0.f;
    for (int c = l; c < CH; c += 16) p += xs[c]*arow[c];
#pragma unroll
    for (int off = 8; off; off >>= 1)
        p += __shfl_xor_sync(0xffffffffu, p, off);
    if (l == 0) {
        if (g < 8) g_xaq[m*RANK + g] = p;
        else       g_xav[m*RANK + (g-8)] = p;
    }
}

// ---------------- kernel 2/4: 128x128x8 SGEMM (NT), fused epilogues --------
// C[m,n] = sum_k A[m,k]*W[n,k]  (+ bias)
// mode 1: QKV — add LoRA-B term on q/v columns, scatter to g_q/g_k/g_v
// mode 0: proj — A = g_ctx, plain bias, write to out
__global__ __launch_bounds__(256)
void gemm_nt(const float* __restrict__ Ain, const float* __restrict__ W,
             const float* __restrict__ bias,
             const float* __restrict__ lqb, const float* __restrict__ lvb,
             float* __restrict__ out, int K, int mode)
{
    const float* A = (mode == 1) ? Ain : g_ctx;
    __shared__ float As[8*128];
    __shared__ float Bs[8*128];
    int tid = threadIdx.x;
    int tx = tid & 15, ty = tid >> 4;
    int bm = blockIdx.y, bn = blockIdx.x;

    float acc[8][8];
#pragma unroll
    for (int i = 0; i < 8; i++)
#pragma unroll
        for (int j = 0; j < 8; j++) acc[i][j] = 0.f;

    int lr  = tid >> 1;            // 0..127
    int lk4 = (tid & 1) << 2;      // 0 or 4
    const float* Abase = A + (size_t)(bm*128 + lr)*K;
    const float* Wbase = W + (size_t)(bn*128 + lr)*K;

    for (int kb = 0; kb < K; kb += 8) {
        float4 avv = *(const float4*)(Abase + kb + lk4);
        float4 wvv = *(const float4*)(Wbase + kb + lk4);
        As[(lk4+0)*128 + lr] = avv.x;
        As[(lk4+1)*128 + lr] = avv.y;
        As[(lk4+2)*128 + lr] = avv.z;
        As[(lk4+3)*128 + lr] = avv.w;
        Bs[(lk4+0)*128 + lr] = wvv.x;
        Bs[(lk4+1)*128 + lr] = wvv.y;
        Bs[(lk4+2)*128 + lr] = wvv.z;
        Bs[(lk4+3)*128 + lr] = wvv.w;
        __syncthreads();
#pragma unroll
        for (int k = 0; k < 8; k++) {
            float a[8], b[8];
#pragma unroll
            for (int i = 0; i < 8; i++) a[i] = As[k*128 + ty*8 + i];
#pragma unroll
            for (int j = 0; j < 8; j++) b[j] = Bs[k*128 + tx*8 + j];
#pragma unroll
            for (int i = 0; i < 8; i++)
#pragma unroll
                for (int j = 0; j < 8; j++) acc[i][j] += a[i]*b[j];
        }
        __syncthreads();
    }

    if (mode == 0) {
#pragma unroll
        for (int i = 0; i < 8; i++) {
            int gm = bm*128 + ty*8 + i;
#pragma unroll
            for (int j = 0; j < 8; j++) {
                int gn = bn*128 + tx*8 + j;
                out[(size_t)gm*CH + gn] = acc[i][j] + bias[gn];
            }
        }
    } else {
#pragma unroll
        for (int i = 0; i < 8; i++) {
            int gm = bm*128 + ty*8 + i;
            int b  = gm >> 10, n = gm & 1023;
            const float* xq = g_xaq + gm*RANK;
            const float* xv = g_xav + gm*RANK;
#pragma unroll
            for (int j = 0; j < 8; j++) {
                int gn = bn*128 + tx*8 + j;
                float val = acc[i][j] + bias[gn];
                int t  = gn >> 10;
                int cj = gn & 1023;
                int h  = cj >> 6, d = cj & 63;
                size_t idx = ((size_t)(b*HEADS + h)*SEQ + n)*HDIM + d;
                if (t == 0) {
                    const float* lb = lqb + cj*RANK;
                    float s = 0.f;
#pragma unroll
                    for (int r = 0; r < RANK; r++) s += xq[r]*lb[r];
                    g_q[idx] = val + LORA_SCALE*s;
                } else if (t == 1) {
                    g_k[idx] = val;
                } else {
                    const float* lb = lvb + cj*RANK;
                    float s = 0.f;
#pragma unroll
                    for (int r = 0; r < RANK; r++) s += xv[r]*lb[r];
                    g_v[idx] = val + LORA_SCALE*s;
                }
            }
        }
    }
}

// ---------------- kernel 3: flash attention (fp32, online softmax) ----------
// grid: (16 q-tiles, 128 b*h). block 256 = 16x16. 64 q-rows, 32-key tiles.
// thread (ty,tx): S micro 4 rows x 2 keys; O micro 4 rows x 4 dims.
__global__ __launch_bounds__(256)
void attn_kernel()
{
    __shared__ float4 qst4[64*16];   // Q transposed: qst4[k*16+g] = rows 4g..4g+3 at dim k
    __shared__ float  kps[64*32];    // phase A: K^T [d][c]; phase B: P [r][k]
    __shared__ float4 vs4[32*16];    // V tile [c][d4]

    int tid = threadIdx.x;
    int tx = tid & 15, ty = tid >> 4;
    int bh = blockIdx.y, qt = blockIdx.x;
    const float* qb = g_q + (size_t)bh*(SEQ*HDIM) + (size_t)qt*64*HDIM;
    const float* kb = g_k + (size_t)bh*(SEQ*HDIM);
    const float* vb = g_v + (size_t)bh*(SEQ*HDIM);

    // load Q tile transposed (64 rows x 64 dims)
    {
        float* qst = (float*)qst4;
        for (int e = tid; e < 1024; e += 256) {
            int r = e & 63, d4 = (e >> 6) << 2;
            float4 v = *(const float4*)(qb + r*HDIM + d4);
            qst[(d4+0)*64 + r] = v.x;
            qst[(d4+1)*64 + r] = v.y;
            qst[(d4+2)*64 + r] = v.z;
            qst[(d4+3)*64 + r] = v.w;
        }
    }

    float o[4][4];
#pragma unroll
    for (int i = 0; i < 4; i++)
#pragma unroll
        for (int j = 0; j < 4; j++) o[i][j] = 0.f;
    float mrow[4] = {-INFINITY, -INFINITY, -INFINITY, -INFINITY};
    float lrow[4] = {0.f, 0.f, 0.f, 0.f};

    for (int kt = 0; kt < 32; kt++) {
        __syncthreads();   // previous tile's PV reads done (and qst visible on kt=0)
        // K tile transposed: kps[d*32 + c]
        for (int e = tid; e < 512; e += 256) {
            int c = e & 31, d4 = (e >> 5) << 2;
            float4 v = *(const float4*)(kb + (size_t)(kt*32 + c)*HDIM + d4);
            kps[(d4+0)*32 + c] = v.x;
            kps[(d4+1)*32 + c] = v.y;
            kps[(d4+2)*32 + c] = v.z;
            kps[(d4+3)*32 + c] = v.w;
        }
        // V tile
        for (int e = tid; e < 512; e += 256) {
            int c = e >> 4, dd = e & 15;
            vs4[c*16 + dd] = *(const float4*)(vb + (size_t)(kt*32 + c)*HDIM + (dd << 2));
        }
        __syncthreads();

        // S = Q K^T
        float s[4][2];
#pragma unroll
        for (int i = 0; i < 4; i++) { s[i][0] = 0.f; s[i][1] = 0.f; }
        const float2* kts2 = (const float2*)kps;
#pragma unroll 8
        for (int k = 0; k < 64; k++) {
            float4 a  = qst4[k*16 + ty];
            float2 bb = kts2[k*16 + tx];
            s[0][0] += a.x*bb.x; s[0][1] += a.x*bb.y;
            s[1][0] += a.y*bb.x; s[1][1] += a.y*bb.y;
            s[2][0] += a.z*bb.x; s[2][1] += a.z*bb.y;
            s[3][0] += a.w*bb.x; s[3][1] += a.w*bb.y;
        }

        // online softmax update (rows live in 16-lane half-warp groups)
        float alpha_[4];
#pragma unroll
        for (int i = 0; i < 4; i++) {
            float v0 = s[i][0]*0.125f, v1 = s[i][1]*0.125f;
            float lm = fmaxf(v0, v1);
#pragma unroll
            for (int off = 8; off; off >>= 1)
                lm = fmaxf(lm, __shfl_xor_sync(0xffffffffu, lm, off));
            float mn = fmaxf(mrow[i], lm);
            float al = __expf(mrow[i] - mn);
            float p0 = __expf(v0 - mn), p1 = __expf(v1 - mn);
            float ls = p0 + p1;
#pragma unroll
            for (int off = 8; off; off >>= 1)
                ls += __shfl_xor_sync(0xffffffffu, ls, off);
            lrow[i] = lrow[i]*al + ls;
            mrow[i] = mn;
            s[i][0] = p0; s[i][1] = p1;
            alpha_[i] = al;
        }

        __syncthreads();   // everyone done reading kps as K^T
#pragma unroll
        for (int i = 0; i < 4; i++) {
            kps[(ty*4+i)*32 + tx*2 + 0] = s[i][0];
            kps[(ty*4+i)*32 + tx*2 + 1] = s[i][1];
            o[i][0] *= alpha_[i]; o[i][1] *= alpha_[i];
            o[i][2] *= alpha_[i]; o[i][3] *= alpha_[i];
        }
        __syncwarp();      // P rows are produced/consumed within the same warp

        // O += P V
#pragma unroll 4
        for (int k = 0; k < 32; k++) {
            float4 vv = vs4[k*16 + tx];
            float p0 = kps[(ty*4+0)*32 + k];
            float p1 = kps[(ty*4+1)*32 + k];
            float p2 = kps[(ty*4+2)*32 + k];
            float p3 = kps[(ty*4+3)*32 + k];
            o[0][0] += p0*vv.x; o[0][1] += p0*vv.y; o[0][2] += p0*vv.z; o[0][3] += p0*vv.w;
            o[1][0] += p1*vv.x; o[1][1] += p1*vv.y; o[1][2] += p1*vv.z; o[1][3] += p1*vv.w;
            o[2][0] += p2*vv.x; o[2][1] += p2*vv.y; o[2][2] += p2*vv.z; o[2][3] += p2*vv.w;
            o[3][0] += p3*vv.x; o[3][1] += p3*vv.y; o[3][2] += p3*vv.z; o[3][3] += p3*vv.w;
        }
    }

    // epilogue: write ctx[b, n, h*64+d]
    int b = bh >> 4, h = bh & 15;
#pragma unroll
    for (int i = 0; i < 4; i++) {
        float inv = 1.0f / lrow[i];
        int n = qt*64 + ty*4 + i;
        float* dst = g_ctx + ((size_t)b*SEQ + n)*CH + h*HDIM + tx*4;
        dst[0] = o[i][0]*inv;
        dst[1] = o[i][1]*inv;
        dst[2] = o[i][2]*inv;
        dst[3] = o[i][3]*inv;
    }
}

// ---------------- launch ----------------------------------------------------
extern "C" void kernel_launch(void* const* d_in, const int* in_sizes, int n_in,
                              void* d_out, int out_size)
{
    (void)in_sizes; (void)n_in; (void)out_size;
    const float* x      = (const float*)d_in[0];
    const float* qkv_w  = (const float*)d_in[1];
    const float* qkv_b  = (const float*)d_in[2];
    const float* proj_w = (const float*)d_in[3];
    const float* proj_b = (const float*)d_in[4];
    const float* lqa    = (const float*)d_in[5];
    const float* lqb    = (const float*)d_in[6];
    const float* lva    = (const float*)d_in[7];
    const float* lvb    = (const float*)d_in[8];
    float* out = (float*)d_out;

    lora_xa_kernel<<<M_TOT, 256>>>(x, lqa, lva);
    gemm_nt<<<dim3(3*CH/128, M_TOT/128), 256>>>(x, qkv_w, qkv_b, lqb, lvb, out, CH, 1);
    attn_kernel<<<dim3(SEQ/64, BATCH*HEADS), 256>>>();
    gemm_nt<<<dim3(CH/128, M_TOT/128), 256>>>(x, proj_w, proj_b, nullptr, nullptr, out, CH, 0);
}

// round 3
// speedup vs baseline: 1.3743x; 1.3743x over previous
#include <cuda_runtime.h>
#include <cuda_bf16.h>
#include <cstdint>
#include <math.h>

#define BATCH 8
#define SEQ   1024
#define CH    1024
#define HEADS 16
#define HDIM  64
#define RANK  8
#define M_TOT (BATCH*SEQ)   // 8192
#define LORA_SCALE 2.0f

// ================= scratch (device globals; no runtime allocation) ==========
__device__ float g_qkv[(size_t)M_TOT*3*CH];          // [B,N,3C] fused qkv (+bias+lora)
__device__ float g_ctx[(size_t)M_TOT*CH];            // attention output [B,N,C]
__device__ float g_xaq[M_TOT*RANK];                  // x @ lora_q_a^T
__device__ float g_xav[M_TOT*RANK];                  // x @ lora_v_a^T
__device__ __nv_bfloat16 g_xhi[(size_t)M_TOT*CH];    // bf16 split of x
__device__ __nv_bfloat16 g_xlo[(size_t)M_TOT*CH];
__device__ __nv_bfloat16 g_wqhi[3*CH*CH];            // bf16 split of qkv_w
__device__ __nv_bfloat16 g_wqlo[3*CH*CH];
__device__ __nv_bfloat16 g_wphi[CH*CH];              // bf16 split of proj_w
__device__ __nv_bfloat16 g_wplo[CH*CH];
__device__ __nv_bfloat16 g_chi[(size_t)M_TOT*CH];    // bf16 split of ctx
__device__ __nv_bfloat16 g_clo[(size_t)M_TOT*CH];

// ================= kernel: fp32 -> (bf16 hi, bf16 lo) split =================
__global__ __launch_bounds__(256)
void convert_split(const float* __restrict__ src, int n4, int which)
{
    __nv_bfloat16 *hi, *lo;
    if (which == 0)      { hi = g_xhi;  lo = g_xlo;  }
    else if (which == 1) { hi = g_wqhi; lo = g_wqlo; }
    else if (which == 2) { hi = g_wphi; lo = g_wplo; }
    else                 { hi = g_chi;  lo = g_clo;  src = g_ctx; }
    int i = blockIdx.x * 256 + threadIdx.x;
    if (i >= n4) return;
    float4 v = ((const float4*)src)[i];
    __nv_bfloat16 hx = __float2bfloat16(v.x);
    __nv_bfloat16 hy = __float2bfloat16(v.y);
    __nv_bfloat16 hz = __float2bfloat16(v.z);
    __nv_bfloat16 hw = __float2bfloat16(v.w);
    ushort4 hs = { __bfloat16_as_ushort(hx), __bfloat16_as_ushort(hy),
                   __bfloat16_as_ushort(hz), __bfloat16_as_ushort(hw) };
    __nv_bfloat16 lx = __float2bfloat16(v.x - __bfloat162float(hx));
    __nv_bfloat16 ly = __float2bfloat16(v.y - __bfloat162float(hy));
    __nv_bfloat16 lz = __float2bfloat16(v.z - __bfloat162float(hz));
    __nv_bfloat16 lw = __float2bfloat16(v.w - __bfloat162float(hw));
    ushort4 ls = { __bfloat16_as_ushort(lx), __bfloat16_as_ushort(ly),
                   __bfloat16_as_ushort(lz), __bfloat16_as_ushort(lw) };
    *(ushort4*)(hi + 4*(size_t)i) = hs;
    *(ushort4*)(lo + 4*(size_t)i) = ls;
}

// ================= kernel: rank-8 LoRA "A" projections ======================
__global__ __launch_bounds__(256)
void lora_xa_kernel(const float* __restrict__ x,
                    const float* __restrict__ aq,
                    const float* __restrict__ av)
{
    __shared__ float xs[CH];
    int m = blockIdx.x;
    const float* xr = x + (size_t)m*CH;
    for (int c = threadIdx.x; c < CH; c += 256) xs[c] = xr[c];
    __syncthreads();
    int g = threadIdx.x >> 4;
    int l = threadIdx.x & 15;
    const float* arow = (g < 8) ? (aq + g*CH) : (av + (g-8)*CH);
    float p = 0.f;
    for (int c = l; c < CH; c += 16) p += xs[c]*arow[c];
#pragma unroll
    for (int off = 8; off; off >>= 1)
        p += __shfl_xor_sync(0xffffffffu, p, off);
    if (l == 0) {
        if (g < 8) g_xaq[m*RANK + g] = p;
        else       g_xav[m*RANK + (g-8)] = p;
    }
}

// ================= kernel: warp-MMA bf16-split GEMM (128x128 tiles) =========
// C[m,n] = sum_k' A''[m,k']*B''[n,k'] over K'=3072 (Ah|Al|Ah x Bh|Bh|Bl)
// mma.sync m16n8k16 bf16 -> f32.  8 warps: warp (wm=w>>1, wn=w&1) owns 32x64.
// smem: rows padded to 20 words (80B) -> conflict-free 32-bit fragment loads.
// mode 1: out=g_qkv[m][3072], +bias, +LoRA(q/v).  mode 0: out=param, +bias.
#define KB 32
#define NCH 96    // 3072/32
__global__ void __launch_bounds__(256)
wgemm(const float* __restrict__ bias,
      const float* __restrict__ lqb, const float* __restrict__ lvb,
      float* __restrict__ outp, int Nout, int mode)
{
    __shared__ uint32_t As32[2][128*20];
    __shared__ uint32_t Bs32[2][128*20];
    int tid = threadIdx.x;
    int w = tid >> 5, l = tid & 31;
    int t = l & 3, g = l >> 2;
    int wm = w >> 1, wn = w & 1;
    int bm = blockIdx.y, bn = blockIdx.x;
    int am0 = bm*128, bn0 = bn*128;

    const __nv_bfloat16 *Ahi, *Alo, *Bhi, *Blo;
    float* out;
    if (mode == 1) { Ahi = g_xhi; Alo = g_xlo; Bhi = g_wqhi; Blo = g_wqlo; out = g_qkv; }
    else           { Ahi = g_chi; Alo = g_clo; Bhi = g_wphi; Blo = g_wplo; out = outp;  }

    float acc[2][8][4];
#pragma unroll
    for (int mi = 0; mi < 2; mi++)
#pragma unroll
        for (int ni = 0; ni < 8; ni++)
#pragma unroll
            for (int e = 0; e < 4; e++) acc[mi][ni][e] = 0.f;

    int seg0 = tid, seg1 = tid + 256;
    int r0 = seg0 >> 2, s0 = (seg0 & 3) << 3;   // 8-elem offset
    int r1 = seg1 >> 2, s1 = (seg1 & 3) << 3;

    uint4 ar0, ar1, br0, br1;

    auto gload = [&](int c) {
        int term = c >> 5;
        int kin = (c & 31) << 5;
        const __nv_bfloat16* Asrc = (term == 1) ? Alo : Ahi;
        const __nv_bfloat16* Bsrc = (term == 2) ? Blo : Bhi;
        ar0 = *(const uint4*)(Asrc + (((size_t)(am0 + r0)) << 10) + kin + s0);
        ar1 = *(const uint4*)(Asrc + (((size_t)(am0 + r1)) << 10) + kin + s1);
        br0 = *(const uint4*)(Bsrc + (((size_t)(bn0 + r0)) << 10) + kin + s0);
        br1 = *(const uint4*)(Bsrc + (((size_t)(bn0 + r1)) << 10) + kin + s1);
    };
    auto sstore = [&](int buf) {
        *(uint4*)&As32[buf][r0*20 + (s0 >> 1)] = ar0;
        *(uint4*)&As32[buf][r1*20 + (s1 >> 1)] = ar1;
        *(uint4*)&Bs32[buf][r0*20 + (s0 >> 1)] = br0;
        *(uint4*)&Bs32[buf][r1*20 + (s1 >> 1)] = br1;
    };

    gload(0);
    sstore(0);

    for (int c = 0; c < NCH; c++) {
        __syncthreads();
        int buf = c & 1;
        if (c + 1 < NCH) gload(c + 1);
        const uint32_t* Ab = As32[buf];
        const uint32_t* Bb = Bs32[buf];
#pragma unroll
        for (int kk8 = 0; kk8 < 16; kk8 += 8) {       // two k16 halves
            uint32_t af[2][4];
#pragma unroll
            for (int mi = 0; mi < 2; mi++) {
                int r = wm*32 + mi*16 + g;
                af[mi][0] = Ab[r*20       + kk8 + t];
                af[mi][1] = Ab[(r+8)*20   + kk8 + t];
                af[mi][2] = Ab[r*20       + kk8 + 4 + t];
                af[mi][3] = Ab[(r+8)*20   + kk8 + 4 + t];
            }
            uint32_t bfr[8][2];
#pragma unroll
            for (int ni = 0; ni < 8; ni++) {
                int n = wn*64 + ni*8 + g;
                bfr[ni][0] = Bb[n*20 + kk8 + t];
                bfr[ni][1] = Bb[n*20 + kk8 + 4 + t];
            }
#pragma unroll
            for (int mi = 0; mi < 2; mi++)
#pragma unroll
                for (int ni = 0; ni < 8; ni++) {
                    float* cc = acc[mi][ni];
                    asm volatile(
                        "mma.sync.aligned.m16n8k16.row.col.f32.bf16.bf16.f32 "
                        "{%0,%1,%2,%3}, {%4,%5,%6,%7}, {%8,%9}, {%0,%1,%2,%3};"
                        : "+f"(cc[0]), "+f"(cc[1]), "+f"(cc[2]), "+f"(cc[3])
                        : "r"(af[mi][0]), "r"(af[mi][1]), "r"(af[mi][2]), "r"(af[mi][3]),
                          "r"(bfr[ni][0]), "r"(bfr[ni][1]));
                }
        }
        if (c + 1 < NCH) sstore(buf ^ 1);
    }

    // ---------------- epilogue -------------------------------------------
    int treg = (mode == 1) ? (bn >> 3) : 1;   // 0:q 1:k/plain 2:v
    if (treg == 1) {
#pragma unroll
        for (int mi = 0; mi < 2; mi++) {
            int gr = am0 + wm*32 + mi*16 + g;
#pragma unroll
            for (int ni = 0; ni < 8; ni++) {
                int col = bn0 + wn*64 + ni*8 + 2*t;
                float b0 = bias[col], b1 = bias[col+1];
                float2 v0 = { acc[mi][ni][0] + b0, acc[mi][ni][1] + b1 };
                float2 v1 = { acc[mi][ni][2] + b0, acc[mi][ni][3] + b1 };
                *(float2*)(out + (size_t)gr*Nout + col)     = v0;
                *(float2*)(out + (size_t)(gr+8)*Nout + col) = v1;
            }
        }
    } else {
        const float* lbase = (treg == 0) ? lqb : lvb;
        int coff = (treg == 2) ? 2048 : 0;
        float* lbs = (float*)&As32[0][0];   // 128 cols x 8 = 4KB (buf0 no longer read)
        *(float4*)&lbs[tid*4] =
            *(const float4*)&lbase[((size_t)(bn0 - coff))*RANK + tid*4];
        __syncthreads();
        const float* xsrc = (treg == 0) ? g_xaq : g_xav;
        float xa_[2][2][8];
#pragma unroll
        for (int mi = 0; mi < 2; mi++)
#pragma unroll
            for (int h = 0; h < 2; h++) {
                int gr = am0 + wm*32 + mi*16 + g + h*8;
                const float4* xp = (const float4*)(xsrc + (size_t)gr*RANK);
                float4 x0 = xp[0], x1 = xp[1];
                xa_[mi][h][0]=x0.x; xa_[mi][h][1]=x0.y; xa_[mi][h][2]=x0.z; xa_[mi][h][3]=x0.w;
                xa_[mi][h][4]=x1.x; xa_[mi][h][5]=x1.y; xa_[mi][h][6]=x1.z; xa_[mi][h][7]=x1.w;
            }
#pragma unroll
        for (int mi = 0; mi < 2; mi++) {
            int gr = am0 + wm*32 + mi*16 + g;
#pragma unroll
            for (int ni = 0; ni < 8; ni++) {
                int lcol = wn*64 + ni*8 + 2*t;
                int col = bn0 + lcol;
                const float* lb0 = lbs + lcol*RANK;
                const float* lb1 = lbs + (lcol+1)*RANK;
                float s00=0.f, s01=0.f, s10=0.f, s11=0.f;
#pragma unroll
                for (int r = 0; r < 8; r++) {
                    s00 += xa_[mi][0][r]*lb0[r];
                    s01 += xa_[mi][0][r]*lb1[r];
                    s10 += xa_[mi][1][r]*lb0[r];
                    s11 += xa_[mi][1][r]*lb1[r];
                }
                float b0 = bias[col], b1 = bias[col+1];
                float2 v0 = { acc[mi][ni][0] + b0 + LORA_SCALE*s00,
                              acc[mi][ni][1] + b1 + LORA_SCALE*s01 };
                float2 v1 = { acc[mi][ni][2] + b0 + LORA_SCALE*s10,
                              acc[mi][ni][3] + b1 + LORA_SCALE*s11 };
                *(float2*)(out + (size_t)gr*Nout + col)     = v0;
                *(float2*)(out + (size_t)(gr+8)*Nout + col) = v1;
            }
        }
    }
}

// ================= kernel: flash attention (fp32, online softmax) ===========
// reads q/k/v from g_qkv [B,N,3C]; writes g_ctx [B,N,C]
__global__ __launch_bounds__(256)
void attn_kernel()
{
    __shared__ float4 qst4[64*16];   // Q^T
    __shared__ float  kps[64*32];    // K^T then P
    __shared__ float4 vs4[32*16];    // V tile

    int tid = threadIdx.x;
    int tx = tid & 15, ty = tid >> 4;
    int bh = blockIdx.y, qt = blockIdx.x;
    int b = bh >> 4, h = bh & 15;
    const float* qb = g_qkv + ((size_t)(b*SEQ + qt*64))*3072 + h*HDIM;
    const float* kb = g_qkv + ((size_t)(b*SEQ))*3072 + CH + h*HDIM;
    const float* vb = g_qkv + ((size_t)(b*SEQ))*3072 + 2*CH + h*HDIM;

    {
        float* qst = (float*)qst4;
        for (int e = tid; e < 1024; e += 256) {
            int r = e & 63, d4 = (e >> 6) << 2;
            float4 v = *(const float4*)(qb + (size_t)r*3072 + d4);
            qst[(d4+0)*64 + r] = v.x;
            qst[(d4+1)*64 + r] = v.y;
            qst[(d4+2)*64 + r] = v.z;
            qst[(d4+3)*64 + r] = v.w;
        }
    }

    float o[4][4];
#pragma unroll
    for (int i = 0; i < 4; i++)
#pragma unroll
        for (int j = 0; j < 4; j++) o[i][j] = 0.f;
    float mrow[4] = {-INFINITY, -INFINITY, -INFINITY, -INFINITY};
    float lrow[4] = {0.f, 0.f, 0.f, 0.f};

    for (int kt = 0; kt < 32; kt++) {
        __syncthreads();
        for (int e = tid; e < 512; e += 256) {
            int c = e & 31, d4 = (e >> 5) << 2;
            float4 v = *(const float4*)(kb + (size_t)(kt*32 + c)*3072 + d4);
            kps[(d4+0)*32 + c] = v.x;
            kps[(d4+1)*32 + c] = v.y;
            kps[(d4+2)*32 + c] = v.z;
            kps[(d4+3)*32 + c] = v.w;
        }
        for (int e = tid; e < 512; e += 256) {
            int c = e >> 4, dd = e & 15;
            vs4[c*16 + dd] = *(const float4*)(vb + (size_t)(kt*32 + c)*3072 + (dd << 2));
        }
        __syncthreads();

        float s[4][2];
#pragma unroll
        for (int i = 0; i < 4; i++) { s[i][0] = 0.f; s[i][1] = 0.f; }
        const float2* kts2 = (const float2*)kps;
#pragma unroll 8
        for (int k = 0; k < 64; k++) {
            float4 a  = qst4[k*16 + ty];
            float2 bb = kts2[k*16 + tx];
            s[0][0] += a.x*bb.x; s[0][1] += a.x*bb.y;
            s[1][0] += a.y*bb.x; s[1][1] += a.y*bb.y;
            s[2][0] += a.z*bb.x; s[2][1] += a.z*bb.y;
            s[3][0] += a.w*bb.x; s[3][1] += a.w*bb.y;
        }

        float alpha_[4];
#pragma unroll
        for (int i = 0; i < 4; i++) {
            float v0 = s[i][0]*0.125f, v1 = s[i][1]*0.125f;
            float lm = fmaxf(v0, v1);
#pragma unroll
            for (int off = 8; off; off >>= 1)
                lm = fmaxf(lm, __shfl_xor_sync(0xffffffffu, lm, off));
            float mn = fmaxf(mrow[i], lm);
            float al = __expf(mrow[i] - mn);
            float p0 = __expf(v0 - mn), p1 = __expf(v1 - mn);
            float ls = p0 + p1;
#pragma unroll
            for (int off = 8; off; off >>= 1)
                ls += __shfl_xor_sync(0xffffffffu, ls, off);
            lrow[i] = lrow[i]*al + ls;
            mrow[i] = mn;
            s[i][0] = p0; s[i][1] = p1;
            alpha_[i] = al;
        }

        __syncthreads();
#pragma unroll
        for (int i = 0; i < 4; i++) {
            kps[(ty*4+i)*32 + tx*2 + 0] = s[i][0];
            kps[(ty*4+i)*32 + tx*2 + 1] = s[i][1];
            o[i][0] *= alpha_[i]; o[i][1] *= alpha_[i];
            o[i][2] *= alpha_[i]; o[i][3] *= alpha_[i];
        }
        __syncwarp();

#pragma unroll 4
        for (int k = 0; k < 32; k++) {
            float4 vv = vs4[k*16 + tx];
            float p0 = kps[(ty*4+0)*32 + k];
            float p1 = kps[(ty*4+1)*32 + k];
            float p2 = kps[(ty*4+2)*32 + k];
            float p3 = kps[(ty*4+3)*32 + k];
            o[0][0] += p0*vv.x; o[0][1] += p0*vv.y; o[0][2] += p0*vv.z; o[0][3] += p0*vv.w;
            o[1][0] += p1*vv.x; o[1][1] += p1*vv.y; o[1][2] += p1*vv.z; o[1][3] += p1*vv.w;
            o[2][0] += p2*vv.x; o[2][1] += p2*vv.y; o[2][2] += p2*vv.z; o[2][3] += p2*vv.w;
            o[3][0] += p3*vv.x; o[3][1] += p3*vv.y; o[3][2] += p3*vv.z; o[3][3] += p3*vv.w;
        }
    }

    int bb2 = bh >> 4, hh = bh & 15;
#pragma unroll
    for (int i = 0; i < 4; i++) {
        float inv = 1.0f / lrow[i];
        int n = qt*64 + ty*4 + i;
        float* dst = g_ctx + ((size_t)bb2*SEQ + n)*CH + hh*HDIM + tx*4;
        dst[0] = o[i][0]*inv;
        dst[1] = o[i][1]*inv;
        dst[2] = o[i][2]*inv;
        dst[3] = o[i][3]*inv;
    }
}

// ================= launch ====================================================
extern "C" void kernel_launch(void* const* d_in, const int* in_sizes, int n_in,
                              void* d_out, int out_size)
{
    (void)in_sizes; (void)n_in; (void)out_size;
    const float* x      = (const float*)d_in[0];
    const float* qkv_w  = (const float*)d_in[1];
    const float* qkv_b  = (const float*)d_in[2];
    const float* proj_w = (const float*)d_in[3];
    const float* proj_b = (const float*)d_in[4];
    const float* lqa    = (const float*)d_in[5];
    const float* lqb    = (const float*)d_in[6];
    const float* lva    = (const float*)d_in[7];
    const float* lvb    = (const float*)d_in[8];
    float* out = (float*)d_out;

    convert_split<<<M_TOT*CH/4/256, 256>>>(x,      M_TOT*CH/4,  0);
    convert_split<<<3*CH*CH/4/256,  256>>>(qkv_w,  3*CH*CH/4,   1);
    convert_split<<<CH*CH/4/256,    256>>>(proj_w, CH*CH/4,     2);
    lora_xa_kernel<<<M_TOT, 256>>>(x, lqa, lva);

    wgemm<<<dim3(3*CH/128, M_TOT/128), 256>>>(qkv_b, lqb, lvb, nullptr, 3*CH, 1);
    attn_kernel<<<dim3(SEQ/64, BATCH*HEADS), 256>>>();
    convert_split<<<M_TOT*CH/4/256, 256>>>(nullptr, M_TOT*CH/4, 3);
    wgemm<<<dim3(CH/128, M_TOT/128), 256>>>(proj_b, nullptr, nullptr, out, CH, 0);
}

// round 4
// speedup vs baseline: 2.1935x; 1.5961x over previous
#include <cuda_runtime.h>
#include <cuda_bf16.h>
#include <cstdint>
#include <math.h>

#define BATCH 8
#define SEQ   1024
#define CH    1024
#define HEADS 16
#define HDIM  64
#define RANK  8
#define M_TOT (BATCH*SEQ)   // 8192
#define LORA_SCALE 2.0f

// ================= scratch (device globals; no runtime allocation) ==========
__device__ float g_xaq[M_TOT*RANK];                  // x @ lora_q_a^T
__device__ float g_xav[M_TOT*RANK];                  // x @ lora_v_a^T
__device__ __nv_bfloat16 g_xhi[(size_t)M_TOT*CH];    // bf16 split of x
__device__ __nv_bfloat16 g_xlo[(size_t)M_TOT*CH];
__device__ __nv_bfloat16 g_wqhi[3*CH*CH];            // bf16 split of qkv_w
__device__ __nv_bfloat16 g_wqlo[3*CH*CH];
__device__ __nv_bfloat16 g_wphi[CH*CH];              // bf16 split of proj_w
__device__ __nv_bfloat16 g_wplo[CH*CH];
// qkv, split to bf16 hi/lo by the wgemm epilogue; layout [row=b*N+n][h*64+d]
__device__ __nv_bfloat16 g_qhi[(size_t)M_TOT*CH];
__device__ __nv_bfloat16 g_qlo[(size_t)M_TOT*CH];
__device__ __nv_bfloat16 g_khi[(size_t)M_TOT*CH];
__device__ __nv_bfloat16 g_klo[(size_t)M_TOT*CH];
__device__ __nv_bfloat16 g_vhi[(size_t)M_TOT*CH];
__device__ __nv_bfloat16 g_vlo[(size_t)M_TOT*CH];
// attention output, bf16 hi/lo, written by attn epilogue, read by proj wgemm
__device__ __nv_bfloat16 g_chi[(size_t)M_TOT*CH];
__device__ __nv_bfloat16 g_clo[(size_t)M_TOT*CH];

// ================= small helpers ============================================
__device__ __forceinline__ uint32_t smem_u32(const void* p) {
    uint32_t a;
    asm("{ .reg .u64 t; cvta.to.shared.u64 t, %1; cvt.u32.u64 %0, t; }" : "=r"(a) : "l"(p));
    return a;
}
__device__ __forceinline__ void cp16(uint32_t dst, const void* src) {
    asm volatile("cp.async.cg.shared.global [%0], [%1], 16;" :: "r"(dst), "l"(src));
}
__device__ __forceinline__ void ldm4(uint32_t& r0, uint32_t& r1, uint32_t& r2, uint32_t& r3,
                                     uint32_t addr) {
    asm volatile("ldmatrix.sync.aligned.m8n8.x4.shared.b16 {%0,%1,%2,%3}, [%4];"
                 : "=r"(r0), "=r"(r1), "=r"(r2), "=r"(r3) : "r"(addr));
}
__device__ __forceinline__ void ldm4t(uint32_t& r0, uint32_t& r1, uint32_t& r2, uint32_t& r3,
                                      uint32_t addr) {
    asm volatile("ldmatrix.sync.aligned.m8n8.x4.trans.shared.b16 {%0,%1,%2,%3}, [%4];"
                 : "=r"(r0), "=r"(r1), "=r"(r2), "=r"(r3) : "r"(addr));
}
__device__ __forceinline__ void mma16816(float* c, const uint32_t* a, const uint32_t* b) {
    asm volatile("mma.sync.aligned.m16n8k16.row.col.f32.bf16.bf16.f32 "
                 "{%0,%1,%2,%3}, {%4,%5,%6,%7}, {%8,%9}, {%0,%1,%2,%3};"
                 : "+f"(c[0]), "+f"(c[1]), "+f"(c[2]), "+f"(c[3])
                 : "r"(a[0]), "r"(a[1]), "r"(a[2]), "r"(a[3]), "r"(b[0]), "r"(b[1]));
}
__device__ __forceinline__ void split2(float v0, float v1, uint32_t& whi, uint32_t& wlo) {
    __nv_bfloat16 h0 = __float2bfloat16(v0), h1 = __float2bfloat16(v1);
    __nv_bfloat16 l0 = __float2bfloat16(v0 - __bfloat162float(h0));
    __nv_bfloat16 l1 = __float2bfloat16(v1 - __bfloat162float(h1));
    whi = (uint32_t)__bfloat16_as_ushort(h0) | ((uint32_t)__bfloat16_as_ushort(h1) << 16);
    wlo = (uint32_t)__bfloat16_as_ushort(l0) | ((uint32_t)__bfloat16_as_ushort(l1) << 16);
}

// ================= kernel: fp32 -> (bf16 hi, bf16 lo) split =================
__global__ __launch_bounds__(256)
void convert_split(const float* __restrict__ src, int n4, int which)
{
    __nv_bfloat16 *hi, *lo;
    if (which == 0)      { hi = g_xhi;  lo = g_xlo;  }
    else if (which == 1) { hi = g_wqhi; lo = g_wqlo; }
    else                 { hi = g_wphi; lo = g_wplo; }
    int i = blockIdx.x * 256 + threadIdx.x;
    if (i >= n4) return;
    float4 v = ((const float4*)src)[i];
    uint32_t h0, l0, h1, l1;
    split2(v.x, v.y, h0, l0);
    split2(v.z, v.w, h1, l1);
    *(uint2*)(hi + 4*(size_t)i) = make_uint2(h0, h1);
    *(uint2*)(lo + 4*(size_t)i) = make_uint2(l0, l1);
}

// ================= kernel: rank-8 LoRA "A" projections ======================
__global__ __launch_bounds__(256)
void lora_xa_kernel(const float* __restrict__ x,
                    const float* __restrict__ aq,
                    const float* __restrict__ av)
{
    __shared__ float xs[CH];
    int m = blockIdx.x;
    const float* xr = x + (size_t)m*CH;
    for (int c = threadIdx.x; c < CH; c += 256) xs[c] = xr[c];
    __syncthreads();
    int g = threadIdx.x >> 4;
    int l = threadIdx.x & 15;
    const float* arow = (g < 8) ? (aq + g*CH) : (av + (g-8)*CH);
    float p = 0.f;
    for (int c = l; c < CH; c += 16) p += xs[c]*arow[c];
#pragma unroll
    for (int off = 8; off; off >>= 1)
        p += __shfl_xor_sync(0xffffffffu, p, off);
    if (l == 0) {
        if (g < 8) g_xaq[m*RANK + g] = p;
        else       g_xav[m*RANK + (g-8)] = p;
    }
}

// ================= kernel: warp-MMA bf16-split GEMM (128x128 tiles) =========
// mode 1: A=x, B=qkv_w; epilogue adds bias+LoRA, splits to g_{q,k,v}{hi,lo}
// mode 0: A=ctx(split), B=proj_w; epilogue adds bias, writes fp32 out
#define NCH 96    // 3072/32
__global__ void __launch_bounds__(256)
wgemm(const float* __restrict__ bias,
      const float* __restrict__ lqb, const float* __restrict__ lvb,
      float* __restrict__ outp, int mode)
{
    __shared__ uint32_t As32[2][128*20];
    __shared__ uint32_t Bs32[2][128*20];
    int tid = threadIdx.x;
    int w = tid >> 5, l = tid & 31;
    int t = l & 3, g = l >> 2;
    int wm = w >> 1, wn = w & 1;
    int bm = blockIdx.y, bn = blockIdx.x;
    int am0 = bm*128, bn0 = bn*128;

    const __nv_bfloat16 *Ahi, *Alo, *Bhi, *Blo;
    if (mode == 1) { Ahi = g_xhi; Alo = g_xlo; Bhi = g_wqhi; Blo = g_wqlo; }
    else           { Ahi = g_chi; Alo = g_clo; Bhi = g_wphi; Blo = g_wplo; }

    float acc[2][8][4];
#pragma unroll
    for (int mi = 0; mi < 2; mi++)
#pragma unroll
        for (int ni = 0; ni < 8; ni++)
#pragma unroll
            for (int e = 0; e < 4; e++) acc[mi][ni][e] = 0.f;

    int r0 = tid >> 2, s0 = (tid & 3) << 3;
    int r1 = r0 + 64,  s1 = s0;

    uint4 ar0, ar1, br0, br1;
    auto gload = [&](int c) {
        int term = c >> 5;
        int kin = (c & 31) << 5;
        const __nv_bfloat16* Asrc = (term == 1) ? Alo : Ahi;
        const __nv_bfloat16* Bsrc = (term == 2) ? Blo : Bhi;
        ar0 = *(const uint4*)(Asrc + (((size_t)(am0 + r0)) << 10) + kin + s0);
        ar1 = *(const uint4*)(Asrc + (((size_t)(am0 + r1)) << 10) + kin + s1);
        br0 = *(const uint4*)(Bsrc + (((size_t)(bn0 + r0)) << 10) + kin + s0);
        br1 = *(const uint4*)(Bsrc + (((size_t)(bn0 + r1)) << 10) + kin + s1);
    };
    auto sstore = [&](int buf) {
        *(uint4*)&As32[buf][r0*20 + (s0 >> 1)] = ar0;
        *(uint4*)&As32[buf][r1*20 + (s1 >> 1)] = ar1;
        *(uint4*)&Bs32[buf][r0*20 + (s0 >> 1)] = br0;
        *(uint4*)&Bs32[buf][r1*20 + (s1 >> 1)] = br1;
    };

    gload(0);
    sstore(0);

    for (int c = 0; c < NCH; c++) {
        __syncthreads();
        int buf = c & 1;
        if (c + 1 < NCH) gload(c + 1);
        const uint32_t* Ab = As32[buf];
        const uint32_t* Bb = Bs32[buf];
#pragma unroll
        for (int kk8 = 0; kk8 < 16; kk8 += 8) {
            uint32_t af[2][4];
#pragma unroll
            for (int mi = 0; mi < 2; mi++) {
                int r = wm*32 + mi*16 + g;
                af[mi][0] = Ab[r*20       + kk8 + t];
                af[mi][1] = Ab[(r+8)*20   + kk8 + t];
                af[mi][2] = Ab[r*20       + kk8 + 4 + t];
                af[mi][3] = Ab[(r+8)*20   + kk8 + 4 + t];
            }
            uint32_t bfr[8][2];
#pragma unroll
            for (int ni = 0; ni < 8; ni++) {
                int n = wn*64 + ni*8 + g;
                bfr[ni][0] = Bb[n*20 + kk8 + t];
                bfr[ni][1] = Bb[n*20 + kk8 + 4 + t];
            }
#pragma unroll
            for (int mi = 0; mi < 2; mi++)
#pragma unroll
                for (int ni = 0; ni < 8; ni++)
                    mma16816(acc[mi][ni], af[mi], bfr[ni]);
        }
        if (c + 1 < NCH) sstore(buf ^ 1);
    }

    // ---------------- epilogue -------------------------------------------
    if (mode == 0) {
#pragma unroll
        for (int mi = 0; mi < 2; mi++) {
            int gr = am0 + wm*32 + mi*16 + g;
#pragma unroll
            for (int ni = 0; ni < 8; ni++) {
                int col = bn0 + wn*64 + ni*8 + 2*t;
                float b0 = bias[col], b1 = bias[col+1];
                float2 v0 = { acc[mi][ni][0] + b0, acc[mi][ni][1] + b1 };
                float2 v1 = { acc[mi][ni][2] + b0, acc[mi][ni][3] + b1 };
                *(float2*)(outp + (size_t)gr*CH + col)     = v0;
                *(float2*)(outp + (size_t)(gr+8)*CH + col) = v1;
            }
        }
        return;
    }
    // mode 1: bias + (LoRA for q,v), then bf16 hi/lo split stores
    int treg = bn >> 3;   // 0:q 1:k 2:v
    __nv_bfloat16 *dh, *dl; int cb;
    if (treg == 0)      { dh = g_qhi; dl = g_qlo; cb = 0;    }
    else if (treg == 1) { dh = g_khi; dl = g_klo; cb = 1024; }
    else                { dh = g_vhi; dl = g_vlo; cb = 2048; }

    float lsum[2][8][4];   // lora contribution per acc element
#pragma unroll
    for (int mi = 0; mi < 2; mi++)
#pragma unroll
        for (int ni = 0; ni < 8; ni++)
#pragma unroll
            for (int e = 0; e < 4; e++) lsum[mi][ni][e] = 0.f;

    if (treg != 1) {
        const float* lbase = (treg == 0) ? lqb : lvb;
        float* lbs = (float*)&As32[0][0];
        *(float4*)&lbs[tid*4] =
            *(const float4*)&lbase[((size_t)(bn0 - cb))*RANK + tid*4];
        __syncthreads();
        const float* xsrc = (treg == 0) ? g_xaq : g_xav;
        float xa_[2][2][8];
#pragma unroll
        for (int mi = 0; mi < 2; mi++)
#pragma unroll
            for (int h = 0; h < 2; h++) {
                int gr = am0 + wm*32 + mi*16 + g + h*8;
                const float4* xp = (const float4*)(xsrc + (size_t)gr*RANK);
                float4 x0 = xp[0], x1 = xp[1];
                xa_[mi][h][0]=x0.x; xa_[mi][h][1]=x0.y; xa_[mi][h][2]=x0.z; xa_[mi][h][3]=x0.w;
                xa_[mi][h][4]=x1.x; xa_[mi][h][5]=x1.y; xa_[mi][h][6]=x1.z; xa_[mi][h][7]=x1.w;
            }
#pragma unroll
        for (int mi = 0; mi < 2; mi++)
#pragma unroll
            for (int ni = 0; ni < 8; ni++) {
                int lcol = wn*64 + ni*8 + 2*t;
                const float* lb0 = lbs + lcol*RANK;
                const float* lb1 = lbs + (lcol+1)*RANK;
                float s00=0.f, s01=0.f, s10=0.f, s11=0.f;
#pragma unroll
                for (int r = 0; r < 8; r++) {
                    s00 += xa_[mi][0][r]*lb0[r];
                    s01 += xa_[mi][0][r]*lb1[r];
                    s10 += xa_[mi][1][r]*lb0[r];
                    s11 += xa_[mi][1][r]*lb1[r];
                }
                lsum[mi][ni][0] = LORA_SCALE*s00; lsum[mi][ni][1] = LORA_SCALE*s01;
                lsum[mi][ni][2] = LORA_SCALE*s10; lsum[mi][ni][3] = LORA_SCALE*s11;
            }
    }
#pragma unroll
    for (int mi = 0; mi < 2; mi++) {
        int gr = am0 + wm*32 + mi*16 + g;
#pragma unroll
        for (int ni = 0; ni < 8; ni++) {
            int col = bn0 + wn*64 + ni*8 + 2*t;
            float b0 = bias[col], b1 = bias[col+1];
            float v00 = acc[mi][ni][0] + b0 + lsum[mi][ni][0];
            float v01 = acc[mi][ni][1] + b1 + lsum[mi][ni][1];
            float v10 = acc[mi][ni][2] + b0 + lsum[mi][ni][2];
            float v11 = acc[mi][ni][3] + b1 + lsum[mi][ni][3];
            uint32_t h0, l0, h1, l1;
            split2(v00, v01, h0, l0);
            split2(v10, v11, h1, l1);
            int cc = col - cb;
            *(uint32_t*)(dh + (size_t)gr*CH + cc)     = h0;
            *(uint32_t*)(dl + (size_t)gr*CH + cc)     = l0;
            *(uint32_t*)(dh + (size_t)(gr+8)*CH + cc) = h1;
            *(uint32_t*)(dl + (size_t)(gr+8)*CH + cc) = l1;
        }
    }
}

// ================= kernel: flash attention via mma.sync =====================
// grid (8 qtiles, 128 bh), 256 thr = 8 warps, each warp 16 q-rows.
// key tiles of 64, cp.async double buffered. 3-term bf16 split on S and PV.
// smem layout (144B padded rows):
//   [0]      K: [2 buf][hi/lo][64 keys][144B]
//   [36864]  V: same
//   [73728]  Q: [hi/lo][128 rows][144B]
#define ATT_SMEM (36864*2 + 18432*2)
__global__ void __launch_bounds__(256, 1)
attn_mma()
{
    extern __shared__ char sm_[];
    uint32_t sb = smem_u32(sm_);
    const uint32_t koff = 0, voff = 36864, qoff = 73728;
    int tid = threadIdx.x;
    int w = tid >> 5, l = tid & 31;
    int t = l & 3, g = l >> 2;
    int qt = blockIdx.x, bh = blockIdx.y;
    int b = bh >> 4, h = bh & 15;
    const size_t rowq0 = (size_t)(b*SEQ + qt*128);
    const size_t rowk0 = (size_t)(b*SEQ);
    const int hc = h*HDIM;

    // ---- prologue: Q (hi/lo) + tile 0 (K/V hi/lo) via cp.async, one group --
#pragma unroll
    for (int i = 0; i < 8; i++) {
        int tk = tid + i*256;                 // 0..2047
        int hl = tk >> 10, r = (tk >> 3) & 127, c = tk & 7;
        uint32_t dst = sb + qoff + hl*18432 + r*144 + c*16;
        const __nv_bfloat16* src = (hl ? g_qlo : g_qhi) + (rowq0 + r)*CH + hc + c*8;
        cp16(dst, src);
    }
#pragma unroll
    for (int i = 0; i < 8; i++) {
        int tk = tid + i*256;
        int arr = tk >> 9, r = (tk >> 3) & 63, c = tk & 7;
        int kv = arr >> 1, hl = arr & 1;
        uint32_t dst = sb + (kv ? voff : koff) + hl*9216 + r*144 + c*16;
        const __nv_bfloat16* src =
            (kv ? (hl ? g_vlo : g_vhi) : (hl ? g_klo : g_khi)) + (rowk0 + r)*CH + hc + c*8;
        cp16(dst, src);
    }
    asm volatile("cp.async.commit_group;");

    uint32_t qh[4][4], ql[4][4];   // Q fragments, all 4 k-steps, hi/lo
    float o[8][4];
#pragma unroll
    for (int j = 0; j < 8; j++)
#pragma unroll
        for (int e = 0; e < 4; e++) o[j][e] = 0.f;
    float mrow[2] = {-INFINITY, -INFINITY};
    float lrow[2] = {0.f, 0.f};
    const int wrow = w*16;

    for (int kt = 0; kt < 16; kt++) {
        __syncthreads();   // everyone done reading the buffer we are about to fill
        int buf = kt & 1;
        if (kt + 1 < 16) {
            int nb = buf ^ 1;
#pragma unroll
            for (int i = 0; i < 8; i++) {
                int tk = tid + i*256;
                int arr = tk >> 9, r = (tk >> 3) & 63, c = tk & 7;
                int kv = arr >> 1, hl = arr & 1;
                uint32_t dst = sb + (kv ? voff : koff) + nb*18432 + hl*9216 + r*144 + c*16;
                const __nv_bfloat16* src =
                    (kv ? (hl ? g_vlo : g_vhi) : (hl ? g_klo : g_khi))
                    + (rowk0 + (kt+1)*64 + r)*CH + hc + c*8;
                cp16(dst, src);
            }
            asm volatile("cp.async.commit_group;");
            asm volatile("cp.async.wait_group 1;");
        } else {
            asm volatile("cp.async.wait_group 0;");
        }
        __syncthreads();

        if (kt == 0) {
            // extract Q fragments once (Q smem ready)
#pragma unroll
            for (int s = 0; s < 4; s++) {
                uint32_t a = sb + qoff + (wrow + (l & 15))*144 + s*32 + (l >> 4)*16;
                ldm4(qh[s][0], qh[s][1], qh[s][2], qh[s][3], a);
                ldm4(ql[s][0], ql[s][1], ql[s][2], ql[s][3], a + 18432);
            }
        }

        // ---- S = Q K^T (3-term split), 16x64 per warp -----------------------
        float s[8][4];
#pragma unroll
        for (int j = 0; j < 8; j++)
#pragma unroll
            for (int e = 0; e < 4; e++) s[j][e] = 0.f;
        uint32_t kb = sb + koff + buf*18432;
#pragma unroll
        for (int s4 = 0; s4 < 4; s4++) {
            uint32_t kf_hi[8][2], kf_lo[8][2];
#pragma unroll
            for (int jp = 0; jp < 4; jp++) {
                uint32_t a = kb + (jp*16 + (l & 7) + ((l >> 4) & 1)*8)*144
                               + s4*32 + ((l >> 3) & 1)*16;
                ldm4(kf_hi[2*jp][0], kf_hi[2*jp][1], kf_hi[2*jp+1][0], kf_hi[2*jp+1][1], a);
                ldm4(kf_lo[2*jp][0], kf_lo[2*jp][1], kf_lo[2*jp+1][0], kf_lo[2*jp+1][1], a + 9216);
            }
#pragma unroll
            for (int j = 0; j < 8; j++) {
                mma16816(s[j], qh[s4], kf_hi[j]);
                mma16816(s[j], ql[s4], kf_hi[j]);
                mma16816(s[j], qh[s4], kf_lo[j]);
            }
        }

        // ---- online softmax (rows g and g+8 per thread) ---------------------
        float mx0 = -INFINITY, mx1 = -INFINITY;
#pragma unroll
        for (int j = 0; j < 8; j++) {
            s[j][0] *= 0.125f; s[j][1] *= 0.125f; s[j][2] *= 0.125f; s[j][3] *= 0.125f;
            mx0 = fmaxf(mx0, fmaxf(s[j][0], s[j][1]));
            mx1 = fmaxf(mx1, fmaxf(s[j][2], s[j][3]));
        }
        mx0 = fmaxf(mx0, __shfl_xor_sync(0xffffffffu, mx0, 1));
        mx0 = fmaxf(mx0, __shfl_xor_sync(0xffffffffu, mx0, 2));
        mx1 = fmaxf(mx1, __shfl_xor_sync(0xffffffffu, mx1, 1));
        mx1 = fmaxf(mx1, __shfl_xor_sync(0xffffffffu, mx1, 2));
        float nm0 = fmaxf(mrow[0], mx0), nm1 = fmaxf(mrow[1], mx1);
        float al0 = __expf(mrow[0] - nm0), al1 = __expf(mrow[1] - nm1);
        mrow[0] = nm0; mrow[1] = nm1;
        float ls0 = 0.f, ls1 = 0.f;
#pragma unroll
        for (int j = 0; j < 8; j++) {
            s[j][0] = __expf(s[j][0] - nm0);
            s[j][1] = __expf(s[j][1] - nm0);
            s[j][2] = __expf(s[j][2] - nm1);
            s[j][3] = __expf(s[j][3] - nm1);
            ls0 += s[j][0] + s[j][1];
            ls1 += s[j][2] + s[j][3];
        }
        ls0 += __shfl_xor_sync(0xffffffffu, ls0, 1);
        ls0 += __shfl_xor_sync(0xffffffffu, ls0, 2);
        ls1 += __shfl_xor_sync(0xffffffffu, ls1, 1);
        ls1 += __shfl_xor_sync(0xffffffffu, ls1, 2);
        lrow[0] = lrow[0]*al0 + ls0;
        lrow[1] = lrow[1]*al1 + ls1;
#pragma unroll
        for (int j = 0; j < 8; j++) {
            o[j][0] *= al0; o[j][1] *= al0;
            o[j][2] *= al1; o[j][3] *= al1;
        }

        // ---- O += P V (3-term split) ----------------------------------------
        uint32_t vbse = sb + voff + buf*18432;
#pragma unroll
        for (int s4 = 0; s4 < 4; s4++) {
            uint32_t pa_hi[4], pa_lo[4];
            split2(s[2*s4][0],   s[2*s4][1],   pa_hi[0], pa_lo[0]);
            split2(s[2*s4][2],   s[2*s4][3],   pa_hi[1], pa_lo[1]);
            split2(s[2*s4+1][0], s[2*s4+1][1], pa_hi[2], pa_lo[2]);
            split2(s[2*s4+1][2], s[2*s4+1][3], pa_hi[3], pa_lo[3]);
            uint32_t vf_hi[8][2], vf_lo[8][2];
#pragma unroll
            for (int jp = 0; jp < 4; jp++) {
                uint32_t a = vbse + (16*s4 + (l & 15))*144 + jp*32 + (l >> 4)*16;
                ldm4t(vf_hi[2*jp][0], vf_hi[2*jp][1], vf_hi[2*jp+1][0], vf_hi[2*jp+1][1], a);
                ldm4t(vf_lo[2*jp][0], vf_lo[2*jp][1], vf_lo[2*jp+1][0], vf_lo[2*jp+1][1], a + 9216);
            }
#pragma unroll
            for (int j = 0; j < 8; j++) {
                mma16816(o[j], pa_hi, vf_hi[j]);
                mma16816(o[j], pa_lo, vf_hi[j]);
                mma16816(o[j], pa_hi, vf_lo[j]);
            }
        }
    }

    // ---- epilogue: O/l -> bf16 hi/lo -> g_chi/g_clo -------------------------
    float inv0 = 1.0f / lrow[0], inv1 = 1.0f / lrow[1];
    size_t r0 = rowq0 + wrow + g;
#pragma unroll
    for (int j = 0; j < 8; j++) {
        int col = hc + j*8 + 2*t;
        uint32_t h0, l0, h1, l1;
        split2(o[j][0]*inv0, o[j][1]*inv0, h0, l0);
        split2(o[j][2]*inv1, o[j][3]*inv1, h1, l1);
        *(uint32_t*)(g_chi + r0*CH + col)     = h0;
        *(uint32_t*)(g_clo + r0*CH + col)     = l0;
        *(uint32_t*)(g_chi + (r0+8)*CH + col) = h1;
        *(uint32_t*)(g_clo + (r0+8)*CH + col) = l1;
    }
}

// ================= launch ====================================================
extern "C" void kernel_launch(void* const* d_in, const int* in_sizes, int n_in,
                              void* d_out, int out_size)
{
    (void)in_sizes; (void)n_in; (void)out_size;
    const float* x      = (const float*)d_in[0];
    const float* qkv_w  = (const float*)d_in[1];
    const float* qkv_b  = (const float*)d_in[2];
    const float* proj_w = (const float*)d_in[3];
    const float* proj_b = (const float*)d_in[4];
    const float* lqa    = (const float*)d_in[5];
    const float* lqb    = (const float*)d_in[6];
    const float* lva    = (const float*)d_in[7];
    const float* lvb    = (const float*)d_in[8];
    float* out = (float*)d_out;

    cudaFuncSetAttribute(attn_mma, cudaFuncAttributeMaxDynamicSharedMemorySize, ATT_SMEM);

    convert_split<<<M_TOT*CH/4/256, 256>>>(x,      M_TOT*CH/4, 0);
    convert_split<<<3*CH*CH/4/256,  256>>>(qkv_w,  3*CH*CH/4,  1);
    convert_split<<<CH*CH/4/256,    256>>>(proj_w, CH*CH/4,    2);
    lora_xa_kernel<<<M_TOT, 256>>>(x, lqa, lva);

    wgemm<<<dim3(3*CH/128, M_TOT/128), 256>>>(qkv_b, lqb, lvb, nullptr, 1);
    attn_mma<<<dim3(SEQ/128, BATCH*HEADS), 256, ATT_SMEM>>>();
    wgemm<<<dim3(CH/128, M_TOT/128), 256>>>(proj_b, nullptr, nullptr, out, 0);
}

// round 5
// speedup vs baseline: 2.7942x; 1.2739x over previous
#include <cuda_runtime.h>
#include <cuda_bf16.h>
#include <cstdint>
#include <math.h>

#define BATCH 8
#define SEQ   1024
#define CH    1024
#define HEADS 16
#define HDIM  64
#define RANK  8
#define M_TOT (BATCH*SEQ)   // 8192
#define LORA_SCALE 2.0f

// ================= scratch (device globals; no runtime allocation) ==========
__device__ float g_xaq[M_TOT*RANK];                  // x @ lora_q_a^T
__device__ float g_xav[M_TOT*RANK];                  // x @ lora_v_a^T
__device__ __nv_bfloat16 g_xhi[(size_t)M_TOT*CH];    // bf16 split of x
__device__ __nv_bfloat16 g_xlo[(size_t)M_TOT*CH];
__device__ __nv_bfloat16 g_wqhi[3*CH*CH];            // bf16 split of qkv_w
__device__ __nv_bfloat16 g_wqlo[3*CH*CH];
__device__ __nv_bfloat16 g_wphi[CH*CH];              // bf16 split of proj_w
__device__ __nv_bfloat16 g_wplo[CH*CH];
// qkv, split to bf16 hi/lo by the wgemm epilogue; layout [row=b*N+n][h*64+d]
__device__ __nv_bfloat16 g_qhi[(size_t)M_TOT*CH];
__device__ __nv_bfloat16 g_qlo[(size_t)M_TOT*CH];
__device__ __nv_bfloat16 g_khi[(size_t)M_TOT*CH];
__device__ __nv_bfloat16 g_klo[(size_t)M_TOT*CH];
__device__ __nv_bfloat16 g_vhi[(size_t)M_TOT*CH];
__device__ __nv_bfloat16 g_vlo[(size_t)M_TOT*CH];
// attention output, bf16 hi/lo, written by attn epilogue, read by proj wgemm
__device__ __nv_bfloat16 g_chi[(size_t)M_TOT*CH];
__device__ __nv_bfloat16 g_clo[(size_t)M_TOT*CH];

// ================= small helpers ============================================
__device__ __forceinline__ uint32_t smem_u32(const void* p) {
    uint32_t a;
    asm("{ .reg .u64 t; cvta.to.shared.u64 t, %1; cvt.u32.u64 %0, t; }" : "=r"(a) : "l"(p));
    return a;
}
__device__ __forceinline__ void cp16(uint32_t dst, const void* src) {
    asm volatile("cp.async.cg.shared.global [%0], [%1], 16;" :: "r"(dst), "l"(src));
}
__device__ __forceinline__ void ldm4(uint32_t& r0, uint32_t& r1, uint32_t& r2, uint32_t& r3,
                                     uint32_t addr) {
    asm volatile("ldmatrix.sync.aligned.m8n8.x4.shared.b16 {%0,%1,%2,%3}, [%4];"
                 : "=r"(r0), "=r"(r1), "=r"(r2), "=r"(r3) : "r"(addr));
}
__device__ __forceinline__ void ldm4t(uint32_t& r0, uint32_t& r1, uint32_t& r2, uint32_t& r3,
                                      uint32_t addr) {
    asm volatile("ldmatrix.sync.aligned.m8n8.x4.trans.shared.b16 {%0,%1,%2,%3}, [%4];"
                 : "=r"(r0), "=r"(r1), "=r"(r2), "=r"(r3) : "r"(addr));
}
__device__ __forceinline__ void mma16816(float* c, const uint32_t* a, const uint32_t* b) {
    asm volatile("mma.sync.aligned.m16n8k16.row.col.f32.bf16.bf16.f32 "
                 "{%0,%1,%2,%3}, {%4,%5,%6,%7}, {%8,%9}, {%0,%1,%2,%3};"
                 : "+f"(c[0]), "+f"(c[1]), "+f"(c[2]), "+f"(c[3])
                 : "r"(a[0]), "r"(a[1]), "r"(a[2]), "r"(a[3]), "r"(b[0]), "r"(b[1]));
}
__device__ __forceinline__ void split2(float v0, float v1, uint32_t& whi, uint32_t& wlo) {
    __nv_bfloat16 h0 = __float2bfloat16(v0), h1 = __float2bfloat16(v1);
    __nv_bfloat16 l0 = __float2bfloat16(v0 - __bfloat162float(h0));
    __nv_bfloat16 l1 = __float2bfloat16(v1 - __bfloat162float(h1));
    whi = (uint32_t)__bfloat16_as_ushort(h0) | ((uint32_t)__bfloat16_as_ushort(h1) << 16);
    wlo = (uint32_t)__bfloat16_as_ushort(l0) | ((uint32_t)__bfloat16_as_ushort(l1) << 16);
}

// ================= kernel: fp32 -> (bf16 hi, bf16 lo) split =================
__global__ __launch_bounds__(256)
void convert_split(const float* __restrict__ src, int n4, int which)
{
    __nv_bfloat16 *hi, *lo;
    if (which == 0)      { hi = g_xhi;  lo = g_xlo;  }
    else if (which == 1) { hi = g_wqhi; lo = g_wqlo; }
    else                 { hi = g_wphi; lo = g_wplo; }
    int i = blockIdx.x * 256 + threadIdx.x;
    if (i >= n4) return;
    float4 v = ((const float4*)src)[i];
    uint32_t h0, l0, h1, l1;
    split2(v.x, v.y, h0, l0);
    split2(v.z, v.w, h1, l1);
    *(uint2*)(hi + 4*(size_t)i) = make_uint2(h0, h1);
    *(uint2*)(lo + 4*(size_t)i) = make_uint2(l0, l1);
}

// ================= kernel: rank-8 LoRA "A" projections (v2) =================
// 8 rows/block; A (16x1024 f32) staged once in smem; x row in registers.
__global__ __launch_bounds__(256)
void lora_xa2(const float* __restrict__ x,
              const float* __restrict__ aq,
              const float* __restrict__ av)
{
    extern __shared__ float As[];   // 16*1024 floats
    int tid = threadIdx.x;
    const float4* aq4 = (const float4*)aq;
    const float4* av4 = (const float4*)av;
    float4* As4 = (float4*)As;
    for (int i = tid; i < 4096; i += 256)
        As4[i] = (i < 2048) ? aq4[i] : av4[i - 2048];
    __syncthreads();

    int w = tid >> 5, l = tid & 31;
    int m = blockIdx.x*8 + w;
    const float4* xr = (const float4*)(x + (size_t)m*CH);
    float4 xv[8];
#pragma unroll
    for (int jj = 0; jj < 8; jj++) xv[jj] = xr[jj*32 + l];

    float acc[16];
#pragma unroll
    for (int o = 0; o < 16; o++) {
        float s = 0.f;
#pragma unroll
        for (int jj = 0; jj < 8; jj++) {
            float4 a = As4[o*256 + jj*32 + l];
            s += xv[jj].x*a.x + xv[jj].y*a.y + xv[jj].z*a.z + xv[jj].w*a.w;
        }
        acc[o] = s;
    }
#pragma unroll
    for (int o = 0; o < 16; o++)
#pragma unroll
        for (int off = 16; off; off >>= 1)
            acc[o] += __shfl_xor_sync(0xffffffffu, acc[o], off);
    if (l < 8)       g_xaq[m*RANK + l] = acc[l];
    else if (l < 16) g_xav[m*RANK + (l - 8)] = acc[l];
}

// ================= kernel: warp-MMA bf16-split GEMM v2 ======================
// 128x128 CTA tile, K chunks of 64, cp.async double buffer, ldmatrix feeds.
// smem: [buf][A|B][128 rows][144B]  (144B pad -> conflict-free ldmatrix)
// mode 1: A=x, B=qkv_w; epilogue bias+LoRA, splits to g_{q,k,v}{hi,lo}
// mode 0: A=ctx(split), B=proj_w; epilogue bias, fp32 out
#define NCH2 48     // 3072/64
#define WG_SMEM 73728
__global__ void __launch_bounds__(256)
wgemm(const float* __restrict__ bias,
      const float* __restrict__ lqb, const float* __restrict__ lvb,
      float* __restrict__ outp, int mode)
{
    extern __shared__ char wsm[];
    uint32_t sb = smem_u32(wsm);
    int tid = threadIdx.x;
    int w = tid >> 5, l = tid & 31;
    int t = l & 3, g = l >> 2;
    int wm = w >> 1, wn = w & 1;
    int bm = blockIdx.y, bn = blockIdx.x;
    int am0 = bm*128, bn0 = bn*128;

    const __nv_bfloat16 *Ahi, *Alo, *Bhi, *Blo;
    if (mode == 1) { Ahi = g_xhi; Alo = g_xlo; Bhi = g_wqhi; Blo = g_wqlo; }
    else           { Ahi = g_chi; Alo = g_clo; Bhi = g_wphi; Blo = g_wplo; }

    float acc[2][8][4];
#pragma unroll
    for (int mi = 0; mi < 2; mi++)
#pragma unroll
        for (int ni = 0; ni < 8; ni++)
#pragma unroll
            for (int e = 0; e < 4; e++) acc[mi][ni][e] = 0.f;

    auto issue = [&](int c) {
        int term = c >> 4;                 // 0:Ah*Bh 1:Al*Bh 2:Ah*Bl
        int kin = (c & 15) << 6;           // k offset in elements
        const __nv_bfloat16* Asrc = (term == 1) ? Alo : Ahi;
        const __nv_bfloat16* Bsrc = (term == 2) ? Blo : Bhi;
        uint32_t base = sb + (c & 1)*36864;
#pragma unroll
        for (int i = 0; i < 8; i++) {
            int tk = tid + (i << 8);               // 0..2047
            int mat = tk >> 10, r = (tk >> 3) & 127, cc = tk & 7;
            uint32_t dst = base + mat*18432 + r*144 + cc*16;
            const __nv_bfloat16* src = mat
                ? Bsrc + (((size_t)(bn0 + r)) << 10) + kin + cc*8
                : Asrc + (((size_t)(am0 + r)) << 10) + kin + cc*8;
            cp16(dst, src);
        }
        asm volatile("cp.async.commit_group;");
    };

    issue(0);
    for (int c = 0; c < NCH2; c++) {
        if (c + 1 < NCH2) { issue(c + 1); asm volatile("cp.async.wait_group 1;"); }
        else              { asm volatile("cp.async.wait_group 0;"); }
        __syncthreads();
        uint32_t Ab = sb + (c & 1)*36864;
        uint32_t Bb = Ab + 18432;
#pragma unroll
        for (int s = 0; s < 4; s++) {
            uint32_t af[2][4];
#pragma unroll
            for (int mi = 0; mi < 2; mi++) {
                uint32_t a = Ab + (wm*32 + mi*16 + (l & 15))*144 + s*32 + (l >> 4)*16;
                ldm4(af[mi][0], af[mi][1], af[mi][2], af[mi][3], a);
            }
            uint32_t bfr[8][2];
#pragma unroll
            for (int jp = 0; jp < 4; jp++) {
                uint32_t a = Bb + (wn*64 + jp*16 + (l & 7) + ((l >> 4) & 1)*8)*144
                           + s*32 + ((l >> 3) & 1)*16;
                ldm4(bfr[2*jp][0], bfr[2*jp][1], bfr[2*jp+1][0], bfr[2*jp+1][1], a);
            }
#pragma unroll
            for (int mi = 0; mi < 2; mi++)
#pragma unroll
                for (int ni = 0; ni < 8; ni++)
                    mma16816(acc[mi][ni], af[mi], bfr[ni]);
        }
        __syncthreads();
    }

    // ---------------- epilogue -------------------------------------------
    if (mode == 0) {
#pragma unroll
        for (int mi = 0; mi < 2; mi++) {
            int gr = am0 + wm*32 + mi*16 + g;
#pragma unroll
            for (int ni = 0; ni < 8; ni++) {
                int col = bn0 + wn*64 + ni*8 + 2*t;
                float b0 = bias[col], b1 = bias[col+1];
                float2 v0 = { acc[mi][ni][0] + b0, acc[mi][ni][1] + b1 };
                float2 v1 = { acc[mi][ni][2] + b0, acc[mi][ni][3] + b1 };
                *(float2*)(outp + (size_t)gr*CH + col)     = v0;
                *(float2*)(outp + (size_t)(gr+8)*CH + col) = v1;
            }
        }
        return;
    }
    // mode 1: bias + (LoRA for q,v), then bf16 hi/lo split stores
    int treg = bn >> 3;   // 0:q 1:k 2:v
    __nv_bfloat16 *dh, *dl; int cb;
    if (treg == 0)      { dh = g_qhi; dl = g_qlo; cb = 0;    }
    else if (treg == 1) { dh = g_khi; dl = g_klo; cb = 1024; }
    else                { dh = g_vhi; dl = g_vlo; cb = 2048; }

    float lsum[2][8][4];
#pragma unroll
    for (int mi = 0; mi < 2; mi++)
#pragma unroll
        for (int ni = 0; ni < 8; ni++)
#pragma unroll
            for (int e = 0; e < 4; e++) lsum[mi][ni][e] = 0.f;

    if (treg != 1) {
        const float* lbase = (treg == 0) ? lqb : lvb;
        float* lbs = (float*)wsm;     // 128 cols x 8 = 4KB
        *(float4*)&lbs[tid*4] =
            *(const float4*)&lbase[((size_t)(bn0 - cb))*RANK + tid*4];
        __syncthreads();
        const float* xsrc = (treg == 0) ? g_xaq : g_xav;
        float xa_[2][2][8];
#pragma unroll
        for (int mi = 0; mi < 2; mi++)
#pragma unroll
            for (int h = 0; h < 2; h++) {
                int gr = am0 + wm*32 + mi*16 + g + h*8;
                const float4* xp = (const float4*)(xsrc + (size_t)gr*RANK);
                float4 x0 = xp[0], x1 = xp[1];
                xa_[mi][h][0]=x0.x; xa_[mi][h][1]=x0.y; xa_[mi][h][2]=x0.z; xa_[mi][h][3]=x0.w;
                xa_[mi][h][4]=x1.x; xa_[mi][h][5]=x1.y; xa_[mi][h][6]=x1.z; xa_[mi][h][7]=x1.w;
            }
#pragma unroll
        for (int mi = 0; mi < 2; mi++)
#pragma unroll
            for (int ni = 0; ni < 8; ni++) {
                int lcol = wn*64 + ni*8 + 2*t;
                const float* lb0 = lbs + lcol*RANK;
                const float* lb1 = lbs + (lcol+1)*RANK;
                float s00=0.f, s01=0.f, s10=0.f, s11=0.f;
#pragma unroll
                for (int r = 0; r < 8; r++) {
                    s00 += xa_[mi][0][r]*lb0[r];
                    s01 += xa_[mi][0][r]*lb1[r];
                    s10 += xa_[mi][1][r]*lb0[r];
                    s11 += xa_[mi][1][r]*lb1[r];
                }
                lsum[mi][ni][0] = LORA_SCALE*s00; lsum[mi][ni][1] = LORA_SCALE*s01;
                lsum[mi][ni][2] = LORA_SCALE*s10; lsum[mi][ni][3] = LORA_SCALE*s11;
            }
    }
#pragma unroll
    for (int mi = 0; mi < 2; mi++) {
        int gr = am0 + wm*32 + mi*16 + g;
#pragma unroll
        for (int ni = 0; ni < 8; ni++) {
            int col = bn0 + wn*64 + ni*8 + 2*t;
            float b0 = bias[col], b1 = bias[col+1];
            float v00 = acc[mi][ni][0] + b0 + lsum[mi][ni][0];
            float v01 = acc[mi][ni][1] + b1 + lsum[mi][ni][1];
            float v10 = acc[mi][ni][2] + b0 + lsum[mi][ni][2];
            float v11 = acc[mi][ni][3] + b1 + lsum[mi][ni][3];
            uint32_t h0, l0, h1, l1;
            split2(v00, v01, h0, l0);
            split2(v10, v11, h1, l1);
            int cc = col - cb;
            *(uint32_t*)(dh + (size_t)gr*CH + cc)     = h0;
            *(uint32_t*)(dl + (size_t)gr*CH + cc)     = l0;
            *(uint32_t*)(dh + (size_t)(gr+8)*CH + cc) = h1;
            *(uint32_t*)(dl + (size_t)(gr+8)*CH + cc) = l1;
        }
    }
}

// ================= kernel: flash attention via mma.sync =====================
// grid (8 qtiles, 128 bh), 256 thr = 8 warps, each warp 16 q-rows.
// key tiles of 64, cp.async double buffered. 3-term bf16 split on S and PV.
#define ATT_SMEM (36864*2 + 18432*2)
__global__ void __launch_bounds__(256, 1)
attn_mma()
{
    extern __shared__ char sm_[];
    uint32_t sb = smem_u32(sm_);
    const uint32_t koff = 0, voff = 36864, qoff = 73728;
    int tid = threadIdx.x;
    int w = tid >> 5, l = tid & 31;
    int t = l & 3, g = l >> 2;
    int qt = blockIdx.x, bh = blockIdx.y;
    int b = bh >> 4, h = bh & 15;
    const size_t rowq0 = (size_t)(b*SEQ + qt*128);
    const size_t rowk0 = (size_t)(b*SEQ);
    const int hc = h*HDIM;

#pragma unroll
    for (int i = 0; i < 8; i++) {
        int tk = tid + i*256;
        int hl = tk >> 10, r = (tk >> 3) & 127, c = tk & 7;
        uint32_t dst = sb + qoff + hl*18432 + r*144 + c*16;
        const __nv_bfloat16* src = (hl ? g_qlo : g_qhi) + (rowq0 + r)*CH + hc + c*8;
        cp16(dst, src);
    }
#pragma unroll
    for (int i = 0; i < 8; i++) {
        int tk = tid + i*256;
        int arr = tk >> 9, r = (tk >> 3) & 63, c = tk & 7;
        int kv = arr >> 1, hl = arr & 1;
        uint32_t dst = sb + (kv ? voff : koff) + hl*9216 + r*144 + c*16;
        const __nv_bfloat16* src =
            (kv ? (hl ? g_vlo : g_vhi) : (hl ? g_klo : g_khi)) + (rowk0 + r)*CH + hc + c*8;
        cp16(dst, src);
    }
    asm volatile("cp.async.commit_group;");

    uint32_t qh[4][4], ql[4][4];
    float o[8][4];
#pragma unroll
    for (int j = 0; j < 8; j++)
#pragma unroll
        for (int e = 0; e < 4; e++) o[j][e] = 0.f;
    float mrow[2] = {-INFINITY, -INFINITY};
    float lrow[2] = {0.f, 0.f};
    const int wrow = w*16;

    for (int kt = 0; kt < 16; kt++) {
        __syncthreads();
        int buf = kt & 1;
        if (kt + 1 < 16) {
            int nb = buf ^ 1;
#pragma unroll
            for (int i = 0; i < 8; i++) {
                int tk = tid + i*256;
                int arr = tk >> 9, r = (tk >> 3) & 63, c = tk & 7;
                int kv = arr >> 1, hl = arr & 1;
                uint32_t dst = sb + (kv ? voff : koff) + nb*18432 + hl*9216 + r*144 + c*16;
                const __nv_bfloat16* src =
                    (kv ? (hl ? g_vlo : g_vhi) : (hl ? g_klo : g_khi))
                    + (rowk0 + (kt+1)*64 + r)*CH + hc + c*8;
                cp16(dst, src);
            }
            asm volatile("cp.async.commit_group;");
            asm volatile("cp.async.wait_group 1;");
        } else {
            asm volatile("cp.async.wait_group 0;");
        }
        __syncthreads();

        if (kt == 0) {
#pragma unroll
            for (int s = 0; s < 4; s++) {
                uint32_t a = sb + qoff + (wrow + (l & 15))*144 + s*32 + (l >> 4)*16;
                ldm4(qh[s][0], qh[s][1], qh[s][2], qh[s][3], a);
                ldm4(ql[s][0], ql[s][1], ql[s][2], ql[s][3], a + 18432);
            }
        }

        float s[8][4];
#pragma unroll
        for (int j = 0; j < 8; j++)
#pragma unroll
            for (int e = 0; e < 4; e++) s[j][e] = 0.f;
        uint32_t kb = sb + koff + buf*18432;
#pragma unroll
        for (int s4 = 0; s4 < 4; s4++) {
            uint32_t kf_hi[8][2], kf_lo[8][2];
#pragma unroll
            for (int jp = 0; jp < 4; jp++) {
                uint32_t a = kb + (jp*16 + (l & 7) + ((l >> 4) & 1)*8)*144
                               + s4*32 + ((l >> 3) & 1)*16;
                ldm4(kf_hi[2*jp][0], kf_hi[2*jp][1], kf_hi[2*jp+1][0], kf_hi[2*jp+1][1], a);
                ldm4(kf_lo[2*jp][0], kf_lo[2*jp][1], kf_lo[2*jp+1][0], kf_lo[2*jp+1][1], a + 9216);
            }
#pragma unroll
            for (int j = 0; j < 8; j++) {
                mma16816(s[j], qh[s4], kf_hi[j]);
                mma16816(s[j], ql[s4], kf_hi[j]);
                mma16816(s[j], qh[s4], kf_lo[j]);
            }
        }

        float mx0 = -INFINITY, mx1 = -INFINITY;
#pragma unroll
        for (int j = 0; j < 8; j++) {
            s[j][0] *= 0.125f; s[j][1] *= 0.125f; s[j][2] *= 0.125f; s[j][3] *= 0.125f;
            mx0 = fmaxf(mx0, fmaxf(s[j][0], s[j][1]));
            mx1 = fmaxf(mx1, fmaxf(s[j][2], s[j][3]));
        }
        mx0 = fmaxf(mx0, __shfl_xor_sync(0xffffffffu, mx0, 1));
        mx0 = fmaxf(mx0, __shfl_xor_sync(0xffffffffu, mx0, 2));
        mx1 = fmaxf(mx1, __shfl_xor_sync(0xffffffffu, mx1, 1));
        mx1 = fmaxf(mx1, __shfl_xor_sync(0xffffffffu, mx1, 2));
        float nm0 = fmaxf(mrow[0], mx0), nm1 = fmaxf(mrow[1], mx1);
        float al0 = __expf(mrow[0] - nm0), al1 = __expf(mrow[1] - nm1);
        mrow[0] = nm0; mrow[1] = nm1;
        float ls0 = 0.f, ls1 = 0.f;
#pragma unroll
        for (int j = 0; j < 8; j++) {
            s[j][0] = __expf(s[j][0] - nm0);
            s[j][1] = __expf(s[j][1] - nm0);
            s[j][2] = __expf(s[j][2] - nm1);
            s[j][3] = __expf(s[j][3] - nm1);
            ls0 += s[j][0] + s[j][1];
            ls1 += s[j][2] + s[j][3];
        }
        ls0 += __shfl_xor_sync(0xffffffffu, ls0, 1);
        ls0 += __shfl_xor_sync(0xffffffffu, ls0, 2);
        ls1 += __shfl_xor_sync(0xffffffffu, ls1, 1);
        ls1 += __shfl_xor_sync(0xffffffffu, ls1, 2);
        lrow[0] = lrow[0]*al0 + ls0;
        lrow[1] = lrow[1]*al1 + ls1;
#pragma unroll
        for (int j = 0; j < 8; j++) {
            o[j][0] *= al0; o[j][1] *= al0;
            o[j][2] *= al1; o[j][3] *= al1;
        }

        uint32_t vbse = sb + voff + buf*18432;
#pragma unroll
        for (int s4 = 0; s4 < 4; s4++) {
            uint32_t pa_hi[4], pa_lo[4];
            split2(s[2*s4][0],   s[2*s4][1],   pa_hi[0], pa_lo[0]);
            split2(s[2*s4][2],   s[2*s4][3],   pa_hi[1], pa_lo[1]);
            split2(s[2*s4+1][0], s[2*s4+1][1], pa_hi[2], pa_lo[2]);
            split2(s[2*s4+1][2], s[2*s4+1][3], pa_hi[3], pa_lo[3]);
            uint32_t vf_hi[8][2], vf_lo[8][2];
#pragma unroll
            for (int jp = 0; jp < 4; jp++) {
                uint32_t a = vbse + (16*s4 + (l & 15))*144 + jp*32 + (l >> 4)*16;
                ldm4t(vf_hi[2*jp][0], vf_hi[2*jp][1], vf_hi[2*jp+1][0], vf_hi[2*jp+1][1], a);
                ldm4t(vf_lo[2*jp][0], vf_lo[2*jp][1], vf_lo[2*jp+1][0], vf_lo[2*jp+1][1], a + 9216);
            }
#pragma unroll
            for (int j = 0; j < 8; j++) {
                mma16816(o[j], pa_hi, vf_hi[j]);
                mma16816(o[j], pa_lo, vf_hi[j]);
                mma16816(o[j], pa_hi, vf_lo[j]);
            }
        }
    }

    float inv0 = 1.0f / lrow[0], inv1 = 1.0f / lrow[1];
    size_t r0 = rowq0 + wrow + g;
#pragma unroll
    for (int j = 0; j < 8; j++) {
        int col = hc + j*8 + 2*t;
        uint32_t h0, l0, h1, l1;
        split2(o[j][0]*inv0, o[j][1]*inv0, h0, l0);
        split2(o[j][2]*inv1, o[j][3]*inv1, h1, l1);
        *(uint32_t*)(g_chi + r0*CH + col)     = h0;
        *(uint32_t*)(g_clo + r0*CH + col)     = l0;
        *(uint32_t*)(g_chi + (r0+8)*CH + col) = h1;
        *(uint32_t*)(g_clo + (r0+8)*CH + col) = l1;
    }
}

// ================= launch ====================================================
extern "C" void kernel_launch(void* const* d_in, const int* in_sizes, int n_in,
                              void* d_out, int out_size)
{
    (void)in_sizes; (void)n_in; (void)out_size;
    const float* x      = (const float*)d_in[0];
    const float* qkv_w  = (const float*)d_in[1];
    const float* qkv_b  = (const float*)d_in[2];
    const float* proj_w = (const float*)d_in[3];
    const float* proj_b = (const float*)d_in[4];
    const float* lqa    = (const float*)d_in[5];
    const float* lqb    = (const float*)d_in[6];
    const float* lva    = (const float*)d_in[7];
    const float* lvb    = (const float*)d_in[8];
    float* out = (float*)d_out;

    cudaFuncSetAttribute(attn_mma, cudaFuncAttributeMaxDynamicSharedMemorySize, ATT_SMEM);
    cudaFuncSetAttribute(wgemm,    cudaFuncAttributeMaxDynamicSharedMemorySize, WG_SMEM);
    cudaFuncSetAttribute(lora_xa2, cudaFuncAttributeMaxDynamicSharedMemorySize, 65536);

    convert_split<<<M_TOT*CH/4/256, 256>>>(x,      M_TOT*CH/4, 0);
    convert_split<<<3*CH*CH/4/256,  256>>>(qkv_w,  3*CH*CH/4,  1);
    convert_split<<<CH*CH/4/256,    256>>>(proj_w, CH*CH/4,    2);
    lora_xa2<<<M_TOT/8, 256, 65536>>>(x, lqa, lva);

    wgemm<<<dim3(3*CH/128, M_TOT/128), 256, WG_SMEM>>>(qkv_b, lqb, lvb, nullptr, 1);
    attn_mma<<<dim3(SEQ/128, BATCH*HEADS), 256, ATT_SMEM>>>();
    wgemm<<<dim3(CH/128, M_TOT/128), 256, WG_SMEM>>>(proj_b, nullptr, nullptr, out, 0);
}

// round 6
// speedup vs baseline: 3.3217x; 1.1888x over previous
#include <cuda_runtime.h>
#include <cuda_bf16.h>
#include <cstdint>
#include <math.h>

#define BATCH 8
#define SEQ   1024
#define CH    1024
#define HEADS 16
#define HDIM  64
#define RANK  8
#define M_TOT (BATCH*SEQ)   // 8192
#define LORA_SCALE 2.0f
#define SCALEQ 0.18033688011112042f   // 0.125 * log2(e), folded into stored q

// ================= scratch (device globals; no runtime allocation) ==========
__device__ float g_xaq[M_TOT*RANK];                  // x @ lora_q_a^T
__device__ float g_xav[M_TOT*RANK];                  // x @ lora_v_a^T
__device__ __nv_bfloat16 g_xhi[(size_t)M_TOT*CH];    // bf16 split of x
__device__ __nv_bfloat16 g_xlo[(size_t)M_TOT*CH];
__device__ __nv_bfloat16 g_wqhi[3*CH*CH];            // bf16 split of qkv_w
__device__ __nv_bfloat16 g_wqlo[3*CH*CH];
__device__ __nv_bfloat16 g_wphi[CH*CH];              // bf16 split of proj_w
__device__ __nv_bfloat16 g_wplo[CH*CH];
// qkv, split to bf16 hi/lo by the wgemm epilogue; q pre-scaled by SCALEQ
__device__ __nv_bfloat16 g_qhi[(size_t)M_TOT*CH];
__device__ __nv_bfloat16 g_qlo[(size_t)M_TOT*CH];
__device__ __nv_bfloat16 g_khi[(size_t)M_TOT*CH];
__device__ __nv_bfloat16 g_klo[(size_t)M_TOT*CH];
__device__ __nv_bfloat16 g_vhi[(size_t)M_TOT*CH];
__device__ __nv_bfloat16 g_vlo[(size_t)M_TOT*CH];
// attention output, bf16 hi/lo
__device__ __nv_bfloat16 g_chi[(size_t)M_TOT*CH];
__device__ __nv_bfloat16 g_clo[(size_t)M_TOT*CH];

// ================= small helpers ============================================
__device__ __forceinline__ uint32_t smem_u32(const void* p) {
    uint32_t a;
    asm("{ .reg .u64 t; cvta.to.shared.u64 t, %1; cvt.u32.u64 %0, t; }" : "=r"(a) : "l"(p));
    return a;
}
__device__ __forceinline__ void cp16(uint32_t dst, const void* src) {
    asm volatile("cp.async.cg.shared.global [%0], [%1], 16;" :: "r"(dst), "l"(src));
}
__device__ __forceinline__ void ldm4(uint32_t& r0, uint32_t& r1, uint32_t& r2, uint32_t& r3,
                                     uint32_t addr) {
    asm volatile("ldmatrix.sync.aligned.m8n8.x4.shared.b16 {%0,%1,%2,%3}, [%4];"
                 : "=r"(r0), "=r"(r1), "=r"(r2), "=r"(r3) : "r"(addr));
}
__device__ __forceinline__ void ldm4t(uint32_t& r0, uint32_t& r1, uint32_t& r2, uint32_t& r3,
                                      uint32_t addr) {
    asm volatile("ldmatrix.sync.aligned.m8n8.x4.trans.shared.b16 {%0,%1,%2,%3}, [%4];"
                 : "=r"(r0), "=r"(r1), "=r"(r2), "=r"(r3) : "r"(addr));
}
__device__ __forceinline__ void mma16816(float* c, const uint32_t* a, const uint32_t* b) {
    asm volatile("mma.sync.aligned.m16n8k16.row.col.f32.bf16.bf16.f32 "
                 "{%0,%1,%2,%3}, {%4,%5,%6,%7}, {%8,%9}, {%0,%1,%2,%3};"
                 : "+f"(c[0]), "+f"(c[1]), "+f"(c[2]), "+f"(c[3])
                 : "r"(a[0]), "r"(a[1]), "r"(a[2]), "r"(a[3]), "r"(b[0]), "r"(b[1]));
}
__device__ __forceinline__ void split2(float v0, float v1, uint32_t& whi, uint32_t& wlo) {
    __nv_bfloat16 h0 = __float2bfloat16(v0), h1 = __float2bfloat16(v1);
    __nv_bfloat16 l0 = __float2bfloat16(v0 - __bfloat162float(h0));
    __nv_bfloat16 l1 = __float2bfloat16(v1 - __bfloat162float(h1));
    whi = (uint32_t)__bfloat16_as_ushort(h0) | ((uint32_t)__bfloat16_as_ushort(h1) << 16);
    wlo = (uint32_t)__bfloat16_as_ushort(l0) | ((uint32_t)__bfloat16_as_ushort(l1) << 16);
}
__device__ __forceinline__ float ex2(float x) {
    float y; asm("ex2.approx.f32 %0, %1;" : "=f"(y) : "f"(x)); return y;
}

// ================= kernel: fp32 -> (bf16 hi, bf16 lo) split =================
__global__ __launch_bounds__(256)
void convert_split(const float* __restrict__ src, int n4, int which)
{
    __nv_bfloat16 *hi, *lo;
    if (which == 0)      { hi = g_xhi;  lo = g_xlo;  }
    else if (which == 1) { hi = g_wqhi; lo = g_wqlo; }
    else                 { hi = g_wphi; lo = g_wplo; }
    int i = blockIdx.x * 256 + threadIdx.x;
    if (i >= n4) return;
    float4 v = ((const float4*)src)[i];
    uint32_t h0, l0, h1, l1;
    split2(v.x, v.y, h0, l0);
    split2(v.z, v.w, h1, l1);
    *(uint2*)(hi + 4*(size_t)i) = make_uint2(h0, h1);
    *(uint2*)(lo + 4*(size_t)i) = make_uint2(l0, l1);
}

// ================= kernel: rank-8 LoRA "A" projections ======================
__global__ __launch_bounds__(256)
void lora_xa2(const float* __restrict__ x,
              const float* __restrict__ aq,
              const float* __restrict__ av)
{
    extern __shared__ float As[];   // 16*1024 floats
    int tid = threadIdx.x;
    const float4* aq4 = (const float4*)aq;
    const float4* av4 = (const float4*)av;
    float4* As4 = (float4*)As;
    for (int i = tid; i < 4096; i += 256)
        As4[i] = (i < 2048) ? aq4[i] : av4[i - 2048];
    __syncthreads();

    int w = tid >> 5, l = tid & 31;
    int m = blockIdx.x*8 + w;
    const float4* xr = (const float4*)(x + (size_t)m*CH);
    float4 xv[8];
#pragma unroll
    for (int jj = 0; jj < 8; jj++) xv[jj] = xr[jj*32 + l];

    float acc[16];
#pragma unroll
    for (int o = 0; o < 16; o++) {
        float s = 0.f;
#pragma unroll
        for (int jj = 0; jj < 8; jj++) {
            float4 a = As4[o*256 + jj*32 + l];
            s += xv[jj].x*a.x + xv[jj].y*a.y + xv[jj].z*a.z + xv[jj].w*a.w;
        }
        acc[o] = s;
    }
#pragma unroll
    for (int o = 0; o < 16; o++)
#pragma unroll
        for (int off = 16; off; off >>= 1)
            acc[o] += __shfl_xor_sync(0xffffffffu, acc[o], off);
    if (l < 8)       g_xaq[m*RANK + l] = acc[l];
    else if (l < 16) g_xav[m*RANK + (l - 8)] = acc[l];
}

// ================= kernel: warp-MMA bf16-split GEMM v3 ======================
// 128x128 CTA tile, 64-K chunks, 3-stage cp.async ring, ONE sync per chunk.
// smem: 3 stages x (A 18432 + B 18432) = 110592
#define NCH2 48     // 3072/64
#define WG_SMEM 110592
__global__ void __launch_bounds__(256, 2)
wgemm(const float* __restrict__ bias,
      const float* __restrict__ lqb, const float* __restrict__ lvb,
      float* __restrict__ outp, int mode)
{
    extern __shared__ char wsm[];
    uint32_t sb = smem_u32(wsm);
    int tid = threadIdx.x;
    int w = tid >> 5, l = tid & 31;
    int t = l & 3, g = l >> 2;
    int wm = w >> 1, wn = w & 1;
    int bm = blockIdx.y, bn = blockIdx.x;
    int am0 = bm*128, bn0 = bn*128;

    const __nv_bfloat16 *Ahi, *Alo, *Bhi, *Blo;
    if (mode == 1) { Ahi = g_xhi; Alo = g_xlo; Bhi = g_wqhi; Blo = g_wqlo; }
    else           { Ahi = g_chi; Alo = g_clo; Bhi = g_wphi; Blo = g_wplo; }

    float acc[2][8][4];
#pragma unroll
    for (int mi = 0; mi < 2; mi++)
#pragma unroll
        for (int ni = 0; ni < 8; ni++)
#pragma unroll
            for (int e = 0; e < 4; e++) acc[mi][ni][e] = 0.f;

    auto issue = [&](int c) {
        int term = c >> 4;                 // 0:Ah*Bh 1:Al*Bh 2:Ah*Bl
        int kin = (c & 15) << 6;
        const __nv_bfloat16* Asrc = (term == 1) ? Alo : Ahi;
        const __nv_bfloat16* Bsrc = (term == 2) ? Blo : Bhi;
        uint32_t base = sb + (c % 3)*36864;
#pragma unroll
        for (int i = 0; i < 8; i++) {
            int tk = tid + (i << 8);
            int mat = tk >> 10, r = (tk >> 3) & 127, cc = tk & 7;
            uint32_t dst = base + mat*18432 + r*144 + cc*16;
            const __nv_bfloat16* src = mat
                ? Bsrc + (((size_t)(bn0 + r)) << 10) + kin + cc*8
                : Asrc + (((size_t)(am0 + r)) << 10) + kin + cc*8;
            cp16(dst, src);
        }
        asm volatile("cp.async.commit_group;");
    };

    issue(0);
    issue(1);
    for (int c = 0; c < NCH2; c++) {
        if (c < NCH2-1) asm volatile("cp.async.wait_group 1;");
        else            asm volatile("cp.async.wait_group 0;");
        __syncthreads();
        if (c + 2 < NCH2) issue(c + 2);
        uint32_t Ab = sb + (c % 3)*36864;
        uint32_t Bb = Ab + 18432;
#pragma unroll
        for (int s = 0; s < 4; s++) {
            uint32_t af[2][4];
#pragma unroll
            for (int mi = 0; mi < 2; mi++) {
                uint32_t a = Ab + (wm*32 + mi*16 + (l & 15))*144 + s*32 + (l >> 4)*16;
                ldm4(af[mi][0], af[mi][1], af[mi][2], af[mi][3], a);
            }
            uint32_t bfr[8][2];
#pragma unroll
            for (int jp = 0; jp < 4; jp++) {
                uint32_t a = Bb + (wn*64 + jp*16 + (l & 7) + ((l >> 4) & 1)*8)*144
                           + s*32 + ((l >> 3) & 1)*16;
                ldm4(bfr[2*jp][0], bfr[2*jp][1], bfr[2*jp+1][0], bfr[2*jp+1][1], a);
            }
#pragma unroll
            for (int mi = 0; mi < 2; mi++)
#pragma unroll
                for (int ni = 0; ni < 8; ni++)
                    mma16816(acc[mi][ni], af[mi], bfr[ni]);
        }
    }
    __syncthreads();

    // ---------------- epilogue -------------------------------------------
    if (mode == 0) {
#pragma unroll
        for (int mi = 0; mi < 2; mi++) {
            int gr = am0 + wm*32 + mi*16 + g;
#pragma unroll
            for (int ni = 0; ni < 8; ni++) {
                int col = bn0 + wn*64 + ni*8 + 2*t;
                float b0 = bias[col], b1 = bias[col+1];
                float2 v0 = { acc[mi][ni][0] + b0, acc[mi][ni][1] + b1 };
                float2 v1 = { acc[mi][ni][2] + b0, acc[mi][ni][3] + b1 };
                *(float2*)(outp + (size_t)gr*CH + col)     = v0;
                *(float2*)(outp + (size_t)(gr+8)*CH + col) = v1;
            }
        }
        return;
    }
    int treg = bn >> 3;   // 0:q 1:k 2:v
    __nv_bfloat16 *dh, *dl; int cb;
    if (treg == 0)      { dh = g_qhi; dl = g_qlo; cb = 0;    }
    else if (treg == 1) { dh = g_khi; dl = g_klo; cb = 1024; }
    else                { dh = g_vhi; dl = g_vlo; cb = 2048; }

    float lsum[2][8][4];
#pragma unroll
    for (int mi = 0; mi < 2; mi++)
#pragma unroll
        for (int ni = 0; ni < 8; ni++)
#pragma unroll
            for (int e = 0; e < 4; e++) lsum[mi][ni][e] = 0.f;

    if (treg != 1) {
        const float* lbase = (treg == 0) ? lqb : lvb;
        float* lbs = (float*)wsm;
        *(float4*)&lbs[tid*4] =
            *(const float4*)&lbase[((size_t)(bn0 - cb))*RANK + tid*4];
        __syncthreads();
        const float* xsrc = (treg == 0) ? g_xaq : g_xav;
        float xa_[2][2][8];
#pragma unroll
        for (int mi = 0; mi < 2; mi++)
#pragma unroll
            for (int h = 0; h < 2; h++) {
                int gr = am0 + wm*32 + mi*16 + g + h*8;
                const float4* xp = (const float4*)(xsrc + (size_t)gr*RANK);
                float4 x0 = xp[0], x1 = xp[1];
                xa_[mi][h][0]=x0.x; xa_[mi][h][1]=x0.y; xa_[mi][h][2]=x0.z; xa_[mi][h][3]=x0.w;
                xa_[mi][h][4]=x1.x; xa_[mi][h][5]=x1.y; xa_[mi][h][6]=x1.z; xa_[mi][h][7]=x1.w;
            }
#pragma unroll
        for (int mi = 0; mi < 2; mi++)
#pragma unroll
            for (int ni = 0; ni < 8; ni++) {
                int lcol = wn*64 + ni*8 + 2*t;
                const float* lb0 = lbs + lcol*RANK;
                const float* lb1 = lbs + (lcol+1)*RANK;
                float s00=0.f, s01=0.f, s10=0.f, s11=0.f;
#pragma unroll
                for (int r = 0; r < 8; r++) {
                    s00 += xa_[mi][0][r]*lb0[r];
                    s01 += xa_[mi][0][r]*lb1[r];
                    s10 += xa_[mi][1][r]*lb0[r];
                    s11 += xa_[mi][1][r]*lb1[r];
                }
                lsum[mi][ni][0] = LORA_SCALE*s00; lsum[mi][ni][1] = LORA_SCALE*s01;
                lsum[mi][ni][2] = LORA_SCALE*s10; lsum[mi][ni][3] = LORA_SCALE*s11;
            }
    }
    float qsc = (treg == 0) ? SCALEQ : 1.0f;
#pragma unroll
    for (int mi = 0; mi < 2; mi++) {
        int gr = am0 + wm*32 + mi*16 + g;
#pragma unroll
        for (int ni = 0; ni < 8; ni++) {
            int col = bn0 + wn*64 + ni*8 + 2*t;
            float b0 = bias[col], b1 = bias[col+1];
            float v00 = (acc[mi][ni][0] + b0 + lsum[mi][ni][0]) * qsc;
            float v01 = (acc[mi][ni][1] + b1 + lsum[mi][ni][1]) * qsc;
            float v10 = (acc[mi][ni][2] + b0 + lsum[mi][ni][2]) * qsc;
            float v11 = (acc[mi][ni][3] + b1 + lsum[mi][ni][3]) * qsc;
            uint32_t h0, l0, h1, l1;
            split2(v00, v01, h0, l0);
            split2(v10, v11, h1, l1);
            int cc = col - cb;
            *(uint32_t*)(dh + (size_t)gr*CH + cc)     = h0;
            *(uint32_t*)(dl + (size_t)gr*CH + cc)     = l0;
            *(uint32_t*)(dh + (size_t)(gr+8)*CH + cc) = h1;
            *(uint32_t*)(dl + (size_t)(gr+8)*CH + cc) = l1;
        }
    }
}

// ================= kernel: flash attention via mma.sync (v2) ================
// grid (8 qtiles, 128 bh), 8 warps x 16 q-rows. 64-key tiles, 3-stage ring,
// ONE sync per tile. No-max softmax (exp2; scale folded into q upstream).
// smem: 3 stages x (Khi 9216 | Klo 9216 | Vhi 9216 | Vlo 9216) = 110592.
// Q staged through stage 0/1 area before the mainloop, lives in registers.
#define ATT_SMEM 110592
__global__ void __launch_bounds__(256, 2)
attn_mma()
{
    extern __shared__ char sm_[];
    uint32_t sb = smem_u32(sm_);
    int tid = threadIdx.x;
    int w = tid >> 5, l = tid & 31;
    int t = l & 3, g = l >> 2;
    int qt = blockIdx.x, bh = blockIdx.y;
    int b = bh >> 4, h = bh & 15;
    const size_t rowq0 = (size_t)(b*SEQ + qt*128);
    const size_t rowk0 = (size_t)(b*SEQ);
    const int hc = h*HDIM;
    const int wrow = w*16;

    // ---- stage Q through smem, extract fragments ----------------------------
#pragma unroll
    for (int i = 0; i < 8; i++) {
        int tk = tid + i*256;
        int hl = tk >> 10, r = (tk >> 3) & 127, c = tk & 7;
        uint32_t dst = sb + hl*18432 + r*144 + c*16;
        const __nv_bfloat16* src = (hl ? g_qlo : g_qhi) + (rowq0 + r)*CH + hc + c*8;
        cp16(dst, src);
    }
    asm volatile("cp.async.commit_group;");
    asm volatile("cp.async.wait_group 0;");
    __syncthreads();
    uint32_t qh[4][4], ql[4][4];
#pragma unroll
    for (int s = 0; s < 4; s++) {
        uint32_t a = sb + (wrow + (l & 15))*144 + s*32 + (l >> 4)*16;
        ldm4(qh[s][0], qh[s][1], qh[s][2], qh[s][3], a);
        ldm4(ql[s][0], ql[s][1], ql[s][2], ql[s][3], a + 18432);
    }
    __syncthreads();   // all warps done reading Q before K/V overwrite

    auto issue_kv = [&](int kt) {
        uint32_t base = sb + (kt % 3)*36864;
        const size_t row = rowk0 + (size_t)kt*64;
#pragma unroll
        for (int i = 0; i < 8; i++) {
            int tk = tid + (i << 8);
            int arr = tk >> 9, r = (tk >> 3) & 63, c = tk & 7;
            uint32_t dst = base + arr*9216 + r*144 + c*16;
            const __nv_bfloat16* src =
                (arr == 0) ? g_khi : (arr == 1) ? g_klo : (arr == 2) ? g_vhi : g_vlo;
            cp16(dst, src + (row + r)*CH + hc + c*8);
        }
        asm volatile("cp.async.commit_group;");
    };

    float o[8][4];
#pragma unroll
    for (int j = 0; j < 8; j++)
#pragma unroll
        for (int e = 0; e < 4; e++) o[j][e] = 0.f;
    float lr0 = 0.f, lr1 = 0.f;

    issue_kv(0);
    issue_kv(1);
    for (int kt = 0; kt < 16; kt++) {
        if (kt < 15) asm volatile("cp.async.wait_group 1;");
        else         asm volatile("cp.async.wait_group 0;");
        __syncthreads();
        if (kt + 2 < 16) issue_kv(kt + 2);
        uint32_t base = sb + (kt % 3)*36864;

        // ---- S = Q K^T (3-term split) ---------------------------------------
        float s[8][4];
#pragma unroll
        for (int j = 0; j < 8; j++)
#pragma unroll
            for (int e = 0; e < 4; e++) s[j][e] = 0.f;
#pragma unroll
        for (int s4 = 0; s4 < 4; s4++) {
            uint32_t kf_hi[8][2], kf_lo[8][2];
#pragma unroll
            for (int jp = 0; jp < 4; jp++) {
                uint32_t a = base + (jp*16 + (l & 7) + ((l >> 4) & 1)*8)*144
                                  + s4*32 + ((l >> 3) & 1)*16;
                ldm4(kf_hi[2*jp][0], kf_hi[2*jp][1], kf_hi[2*jp+1][0], kf_hi[2*jp+1][1], a);
                ldm4(kf_lo[2*jp][0], kf_lo[2*jp][1], kf_lo[2*jp+1][0], kf_lo[2*jp+1][1], a + 9216);
            }
#pragma unroll
            for (int j = 0; j < 8; j++) {
                mma16816(s[j], qh[s4], kf_hi[j]);
                mma16816(s[j], ql[s4], kf_hi[j]);
                mma16816(s[j], qh[s4], kf_lo[j]);
            }
        }

        // ---- no-max softmax: p = exp2(s), accumulate row sums ---------------
#pragma unroll
        for (int j = 0; j < 8; j++) {
            s[j][0] = ex2(s[j][0]); s[j][1] = ex2(s[j][1]);
            s[j][2] = ex2(s[j][2]); s[j][3] = ex2(s[j][3]);
            lr0 += s[j][0] + s[j][1];
            lr1 += s[j][2] + s[j][3];
        }

        // ---- O += P V (3-term split) -----------------------------------------
        uint32_t vbse = base + 18432;
#pragma unroll
        for (int s4 = 0; s4 < 4; s4++) {
            uint32_t pa_hi[4], pa_lo[4];
            split2(s[2*s4][0],   s[2*s4][1],   pa_hi[0], pa_lo[0]);
            split2(s[2*s4][2],   s[2*s4][3],   pa_hi[1], pa_lo[1]);
            split2(s[2*s4+1][0], s[2*s4+1][1], pa_hi[2], pa_lo[2]);
            split2(s[2*s4+1][2], s[2*s4+1][3], pa_hi[3], pa_lo[3]);
            uint32_t vf_hi[8][2], vf_lo[8][2];
#pragma unroll
            for (int jp = 0; jp < 4; jp++) {
                uint32_t a = vbse + (16*s4 + (l & 15))*144 + jp*32 + (l >> 4)*16;
                ldm4t(vf_hi[2*jp][0], vf_hi[2*jp][1], vf_hi[2*jp+1][0], vf_hi[2*jp+1][1], a);
                ldm4t(vf_lo[2*jp][0], vf_lo[2*jp][1], vf_lo[2*jp+1][0], vf_lo[2*jp+1][1], a + 9216);
            }
#pragma unroll
            for (int j = 0; j < 8; j++) {
                mma16816(o[j], pa_hi, vf_hi[j]);
                mma16816(o[j], pa_lo, vf_hi[j]);
                mma16816(o[j], pa_hi, vf_lo[j]);
            }
        }
    }

    // ---- epilogue ------------------------------------------------------------
    lr0 += __shfl_xor_sync(0xffffffffu, lr0, 1);
    lr0 += __shfl_xor_sync(0xffffffffu, lr0, 2);
    lr1 += __shfl_xor_sync(0xffffffffu, lr1, 1);
    lr1 += __shfl_xor_sync(0xffffffffu, lr1, 2);
    float inv0 = 1.0f / lr0, inv1 = 1.0f / lr1;
    size_t r0 = rowq0 + wrow + g;
#pragma unroll
    for (int j = 0; j < 8; j++) {
        int col = hc + j*8 + 2*t;
        uint32_t h0, l0, h1, l1;
        split2(o[j][0]*inv0, o[j][1]*inv0, h0, l0);
        split2(o[j][2]*inv1, o[j][3]*inv1, h1, l1);
        *(uint32_t*)(g_chi + r0*CH + col)     = h0;
        *(uint32_t*)(g_clo + r0*CH + col)     = l0;
        *(uint32_t*)(g_chi + (r0+8)*CH + col) = h1;
        *(uint32_t*)(g_clo + (r0+8)*CH + col) = l1;
    }
}

// ================= launch ====================================================
extern "C" void kernel_launch(void* const* d_in, const int* in_sizes, int n_in,
                              void* d_out, int out_size)
{
    (void)in_sizes; (void)n_in; (void)out_size;
    const float* x      = (const float*)d_in[0];
    const float* qkv_w  = (const float*)d_in[1];
    const float* qkv_b  = (const float*)d_in[2];
    const float* proj_w = (const float*)d_in[3];
    const float* proj_b = (const float*)d_in[4];
    const float* lqa    = (const float*)d_in[5];
    const float* lqb    = (const float*)d_in[6];
    const float* lva    = (const float*)d_in[7];
    const float* lvb    = (const float*)d_in[8];
    float* out = (float*)d_out;

    cudaFuncSetAttribute(attn_mma, cudaFuncAttributeMaxDynamicSharedMemorySize, ATT_SMEM);
    cudaFuncSetAttribute(wgemm,    cudaFuncAttributeMaxDynamicSharedMemorySize, WG_SMEM);
    cudaFuncSetAttribute(lora_xa2, cudaFuncAttributeMaxDynamicSharedMemorySize, 65536);

    convert_split<<<M_TOT*CH/4/256, 256>>>(x,      M_TOT*CH/4, 0);
    convert_split<<<3*CH*CH/4/256,  256>>>(qkv_w,  3*CH*CH/4,  1);
    convert_split<<<CH*CH/4/256,    256>>>(proj_w, CH*CH/4,    2);
    lora_xa2<<<M_TOT/8, 256, 65536>>>(x, lqa, lva);

    wgemm<<<dim3(3*CH/128, M_TOT/128), 256, WG_SMEM>>>(qkv_b, lqb, lvb, nullptr, 1);
    attn_mma<<<dim3(SEQ/128, BATCH*HEADS), 256, ATT_SMEM>>>();
    wgemm<<<dim3(CH/128, M_TOT/128), 256, WG_SMEM>>>(proj_b, nullptr, nullptr, out, 0);
}

// round 7
// speedup vs baseline: 3.4769x; 1.0467x over previous
#include <cuda_runtime.h>
#include <cuda_bf16.h>
#include <cstdint>
#include <math.h>

#define BATCH 8
#define SEQ   1024
#define CH    1024
#define HEADS 16
#define HDIM  64
#define RANK  8
#define M_TOT (BATCH*SEQ)   // 8192
#define LORA_SCALE 2.0f
#define SCALEQ 0.18033688011112042f   // 0.125 * log2(e), folded into stored q

// ================= scratch (device globals; no runtime allocation) ==========
__device__ float g_xaq[M_TOT*RANK];
__device__ float g_xav[M_TOT*RANK];
__device__ __nv_bfloat16 g_xhi[(size_t)M_TOT*CH];
__device__ __nv_bfloat16 g_xlo[(size_t)M_TOT*CH];
__device__ __nv_bfloat16 g_wqhi[3*CH*CH];
__device__ __nv_bfloat16 g_wqlo[3*CH*CH];
__device__ __nv_bfloat16 g_wphi[CH*CH];
__device__ __nv_bfloat16 g_wplo[CH*CH];
__device__ __nv_bfloat16 g_qhi[(size_t)M_TOT*CH];   // q pre-scaled by SCALEQ
__device__ __nv_bfloat16 g_qlo[(size_t)M_TOT*CH];
__device__ __nv_bfloat16 g_khi[(size_t)M_TOT*CH];
__device__ __nv_bfloat16 g_klo[(size_t)M_TOT*CH];
__device__ __nv_bfloat16 g_vhi[(size_t)M_TOT*CH];
__device__ __nv_bfloat16 g_vlo[(size_t)M_TOT*CH];
__device__ __nv_bfloat16 g_chi[(size_t)M_TOT*CH];
__device__ __nv_bfloat16 g_clo[(size_t)M_TOT*CH];

// ================= small helpers ============================================
__device__ __forceinline__ uint32_t smem_u32(const void* p) {
    uint32_t a;
    asm("{ .reg .u64 t; cvta.to.shared.u64 t, %1; cvt.u32.u64 %0, t; }" : "=r"(a) : "l"(p));
    return a;
}
__device__ __forceinline__ void cp16(uint32_t dst, const void* src) {
    asm volatile("cp.async.cg.shared.global [%0], [%1], 16;" :: "r"(dst), "l"(src));
}
__device__ __forceinline__ void ldm4(uint32_t& r0, uint32_t& r1, uint32_t& r2, uint32_t& r3,
                                     uint32_t addr) {
    asm volatile("ldmatrix.sync.aligned.m8n8.x4.shared.b16 {%0,%1,%2,%3}, [%4];"
                 : "=r"(r0), "=r"(r1), "=r"(r2), "=r"(r3) : "r"(addr));
}
__device__ __forceinline__ void ldm4t(uint32_t& r0, uint32_t& r1, uint32_t& r2, uint32_t& r3,
                                      uint32_t addr) {
    asm volatile("ldmatrix.sync.aligned.m8n8.x4.trans.shared.b16 {%0,%1,%2,%3}, [%4];"
                 : "=r"(r0), "=r"(r1), "=r"(r2), "=r"(r3) : "r"(addr));
}
__device__ __forceinline__ void mma16816(float* c, const uint32_t* a, const uint32_t* b) {
    asm volatile("mma.sync.aligned.m16n8k16.row.col.f32.bf16.bf16.f32 "
                 "{%0,%1,%2,%3}, {%4,%5,%6,%7}, {%8,%9}, {%0,%1,%2,%3};"
                 : "+f"(c[0]), "+f"(c[1]), "+f"(c[2]), "+f"(c[3])
                 : "r"(a[0]), "r"(a[1]), "r"(a[2]), "r"(a[3]), "r"(b[0]), "r"(b[1]));
}
// cheap hi/lo split: hi = truncate-to-bf16 (PRMT), lo = packed-round of residue
__device__ __forceinline__ void split2(float v0, float v1, uint32_t& whi, uint32_t& wlo) {
    uint32_t u0 = __float_as_uint(v0), u1 = __float_as_uint(v1);
    whi = __byte_perm(u0, u1, 0x7632);
    float l0 = v0 - __uint_as_float(u0 & 0xFFFF0000u);
    float l1 = v1 - __uint_as_float(u1 & 0xFFFF0000u);
    asm("cvt.rn.bf16x2.f32 %0, %1, %2;" : "=r"(wlo) : "f"(l1), "f"(l0));
}
__device__ __forceinline__ float ex2(float x) {
    float y; asm("ex2.approx.f32 %0, %1;" : "=f"(y) : "f"(x)); return y;
}

// ================= kernel: fp32 -> (bf16 hi, bf16 lo) split =================
__global__ __launch_bounds__(256)
void convert_split(const float* __restrict__ src, int n4, int which)
{
    __nv_bfloat16 *hi, *lo;
    if (which == 0)      { hi = g_xhi;  lo = g_xlo;  }
    else if (which == 1) { hi = g_wqhi; lo = g_wqlo; }
    else                 { hi = g_wphi; lo = g_wplo; }
    int i = blockIdx.x * 256 + threadIdx.x;
    if (i >= n4) return;
    float4 v = ((const float4*)src)[i];
    uint32_t h0, l0, h1, l1;
    split2(v.x, v.y, h0, l0);
    split2(v.z, v.w, h1, l1);
    *(uint2*)(hi + 4*(size_t)i) = make_uint2(h0, h1);
    *(uint2*)(lo + 4*(size_t)i) = make_uint2(l0, l1);
}

// ================= kernel: rank-8 LoRA "A" projections ======================
__global__ __launch_bounds__(256)
void lora_xa2(const float* __restrict__ x,
              const float* __restrict__ aq,
              const float* __restrict__ av)
{
    extern __shared__ float As[];
    int tid = threadIdx.x;
    const float4* aq4 = (const float4*)aq;
    const float4* av4 = (const float4*)av;
    float4* As4 = (float4*)As;
    for (int i = tid; i < 4096; i += 256)
        As4[i] = (i < 2048) ? aq4[i] : av4[i - 2048];
    __syncthreads();

    int w = tid >> 5, l = tid & 31;
    int m = blockIdx.x*8 + w;
    const float4* xr = (const float4*)(x + (size_t)m*CH);
    float4 xv[8];
#pragma unroll
    for (int jj = 0; jj < 8; jj++) xv[jj] = xr[jj*32 + l];

    float acc[16];
#pragma unroll
    for (int o = 0; o < 16; o++) {
        float s = 0.f;
#pragma unroll
        for (int jj = 0; jj < 8; jj++) {
            float4 a = As4[o*256 + jj*32 + l];
            s += xv[jj].x*a.x + xv[jj].y*a.y + xv[jj].z*a.z + xv[jj].w*a.w;
        }
        acc[o] = s;
    }
#pragma unroll
    for (int o = 0; o < 16; o++)
#pragma unroll
        for (int off = 16; off; off >>= 1)
            acc[o] += __shfl_xor_sync(0xffffffffu, acc[o], off);
    if (l < 8)       g_xaq[m*RANK + l] = acc[l];
    else if (l < 16) g_xav[m*RANK + (l - 8)] = acc[l];
}

// ================= kernel: warp-MMA bf16-split GEMM v4 ======================
// 128x128 CTA tile. K-chunk = 32 ORIGINAL columns; stage holds Ah|Al and
// Bh|Bl together (row = hi 64B | lo 64B | pad 16 -> 144B). 3 split terms are
// in-register passes: 12 LDSM feed 48 MMA per k16 step. 3-stage cp.async
// ring, one sync per chunk.
#define NCHK 32     // 1024/32
#define WG_SMEM 110592
__global__ void __launch_bounds__(256, 2)
wgemm(const float* __restrict__ bias,
      const float* __restrict__ lqb, const float* __restrict__ lvb,
      float* __restrict__ outp, int mode)
{
    extern __shared__ char wsm[];
    uint32_t sb = smem_u32(wsm);
    int tid = threadIdx.x;
    int w = tid >> 5, l = tid & 31;
    int t = l & 3, g = l >> 2;
    int wm = w >> 1, wn = w & 1;
    int bm = blockIdx.y, bn = blockIdx.x;
    int am0 = bm*128, bn0 = bn*128;

    const __nv_bfloat16 *Ahi, *Alo, *Bhi, *Blo;
    if (mode == 1) { Ahi = g_xhi; Alo = g_xlo; Bhi = g_wqhi; Blo = g_wqlo; }
    else           { Ahi = g_chi; Alo = g_clo; Bhi = g_wphi; Blo = g_wplo; }

    float acc[2][8][4];
#pragma unroll
    for (int mi = 0; mi < 2; mi++)
#pragma unroll
        for (int ni = 0; ni < 8; ni++)
#pragma unroll
            for (int e = 0; e < 4; e++) acc[mi][ni][e] = 0.f;

    auto issue = [&](int c) {
        int kin = c << 5;
        uint32_t base = sb + (c % 3)*36864;
#pragma unroll
        for (int i = 0; i < 8; i++) {
            int tk = tid + (i << 8);
            int mat = tk >> 10, r = (tk >> 3) & 127, sub = tk & 7;
            uint32_t dst = base + mat*18432 + r*144 + sub*16;
            int cc = (sub & 3) << 3;
            const __nv_bfloat16* src;
            if (mat == 0) src = ((sub & 4) ? Alo : Ahi) + (((size_t)(am0 + r)) << 10) + kin + cc;
            else          src = ((sub & 4) ? Blo : Bhi) + (((size_t)(bn0 + r)) << 10) + kin + cc;
            cp16(dst, src);
        }
        asm volatile("cp.async.commit_group;");
    };

    issue(0);
    issue(1);
    for (int c = 0; c < NCHK; c++) {
        if (c < NCHK-1) asm volatile("cp.async.wait_group 1;");
        else            asm volatile("cp.async.wait_group 0;");
        __syncthreads();
        if (c + 2 < NCHK) issue(c + 2);
        uint32_t Ab = sb + (c % 3)*36864;
        uint32_t Bb = Ab + 18432;
#pragma unroll
        for (int s = 0; s < 2; s++) {
            uint32_t afh[2][4], afl[2][4];
#pragma unroll
            for (int mi = 0; mi < 2; mi++) {
                uint32_t a0 = Ab + (wm*32 + mi*16 + (l & 15))*144 + s*32 + (l >> 4)*16;
                ldm4(afh[mi][0], afh[mi][1], afh[mi][2], afh[mi][3], a0);
                ldm4(afl[mi][0], afl[mi][1], afl[mi][2], afl[mi][3], a0 + 64);
            }
#pragma unroll
            for (int jp = 0; jp < 4; jp++) {
                uint32_t b0 = Bb + (wn*64 + jp*16 + (l & 7) + ((l >> 4) & 1)*8)*144
                                 + s*32 + ((l >> 3) & 1)*16;
                uint32_t bh[4], bl[4];
                ldm4(bh[0], bh[1], bh[2], bh[3], b0);
                ldm4(bl[0], bl[1], bl[2], bl[3], b0 + 64);
#pragma unroll
                for (int mi = 0; mi < 2; mi++) {
                    mma16816(acc[mi][2*jp],   afh[mi], bh);
                    mma16816(acc[mi][2*jp],   afl[mi], bh);
                    mma16816(acc[mi][2*jp],   afh[mi], bl);
                    mma16816(acc[mi][2*jp+1], afh[mi], bh + 2);
                    mma16816(acc[mi][2*jp+1], afl[mi], bh + 2);
                    mma16816(acc[mi][2*jp+1], afh[mi], bl + 2);
                }
            }
        }
    }
    __syncthreads();

    // ---------------- epilogue -------------------------------------------
    if (mode == 0) {
#pragma unroll
        for (int mi = 0; mi < 2; mi++) {
            int gr = am0 + wm*32 + mi*16 + g;
#pragma unroll
            for (int ni = 0; ni < 8; ni++) {
                int col = bn0 + wn*64 + ni*8 + 2*t;
                float b0 = bias[col], b1 = bias[col+1];
                float2 v0 = { acc[mi][ni][0] + b0, acc[mi][ni][1] + b1 };
                float2 v1 = { acc[mi][ni][2] + b0, acc[mi][ni][3] + b1 };
                *(float2*)(outp + (size_t)gr*CH + col)     = v0;
                *(float2*)(outp + (size_t)(gr+8)*CH + col) = v1;
            }
        }
        return;
    }
    int treg = bn >> 3;   // 0:q 1:k 2:v
    __nv_bfloat16 *dh, *dl; int cb;
    if (treg == 0)      { dh = g_qhi; dl = g_qlo; cb = 0;    }
    else if (treg == 1) { dh = g_khi; dl = g_klo; cb = 1024; }
    else                { dh = g_vhi; dl = g_vlo; cb = 2048; }

    float lsum[2][8][4];
#pragma unroll
    for (int mi = 0; mi < 2; mi++)
#pragma unroll
        for (int ni = 0; ni < 8; ni++)
#pragma unroll
            for (int e = 0; e < 4; e++) lsum[mi][ni][e] = 0.f;

    if (treg != 1) {
        const float* lbase = (treg == 0) ? lqb : lvb;
        float* lbs = (float*)wsm;
        *(float4*)&lbs[tid*4] =
            *(const float4*)&lbase[((size_t)(bn0 - cb))*RANK + tid*4];
        __syncthreads();
        const float* xsrc = (treg == 0) ? g_xaq : g_xav;
        float xa_[2][2][8];
#pragma unroll
        for (int mi = 0; mi < 2; mi++)
#pragma unroll
            for (int h = 0; h < 2; h++) {
                int gr = am0 + wm*32 + mi*16 + g + h*8;
                const float4* xp = (const float4*)(xsrc + (size_t)gr*RANK);
                float4 x0 = xp[0], x1 = xp[1];
                xa_[mi][h][0]=x0.x; xa_[mi][h][1]=x0.y; xa_[mi][h][2]=x0.z; xa_[mi][h][3]=x0.w;
                xa_[mi][h][4]=x1.x; xa_[mi][h][5]=x1.y; xa_[mi][h][6]=x1.z; xa_[mi][h][7]=x1.w;
            }
#pragma unroll
        for (int mi = 0; mi < 2; mi++)
#pragma unroll
            for (int ni = 0; ni < 8; ni++) {
                int lcol = wn*64 + ni*8 + 2*t;
                const float* lb0 = lbs + lcol*RANK;
                const float* lb1 = lbs + (lcol+1)*RANK;
                float s00=0.f, s01=0.f, s10=0.f, s11=0.f;
#pragma unroll
                for (int r = 0; r < 8; r++) {
                    s00 += xa_[mi][0][r]*lb0[r];
                    s01 += xa_[mi][0][r]*lb1[r];
                    s10 += xa_[mi][1][r]*lb0[r];
                    s11 += xa_[mi][1][r]*lb1[r];
                }
                lsum[mi][ni][0] = LORA_SCALE*s00; lsum[mi][ni][1] = LORA_SCALE*s01;
                lsum[mi][ni][2] = LORA_SCALE*s10; lsum[mi][ni][3] = LORA_SCALE*s11;
            }
    }
    float qsc = (treg == 0) ? SCALEQ : 1.0f;
#pragma unroll
    for (int mi = 0; mi < 2; mi++) {
        int gr = am0 + wm*32 + mi*16 + g;
#pragma unroll
        for (int ni = 0; ni < 8; ni++) {
            int col = bn0 + wn*64 + ni*8 + 2*t;
            float b0 = bias[col], b1 = bias[col+1];
            float v00 = (acc[mi][ni][0] + b0 + lsum[mi][ni][0]) * qsc;
            float v01 = (acc[mi][ni][1] + b1 + lsum[mi][ni][1]) * qsc;
            float v10 = (acc[mi][ni][2] + b0 + lsum[mi][ni][2]) * qsc;
            float v11 = (acc[mi][ni][3] + b1 + lsum[mi][ni][3]) * qsc;
            uint32_t h0, l0, h1, l1;
            split2(v00, v01, h0, l0);
            split2(v10, v11, h1, l1);
            int cc = col - cb;
            *(uint32_t*)(dh + (size_t)gr*CH + cc)     = h0;
            *(uint32_t*)(dl + (size_t)gr*CH + cc)     = l0;
            *(uint32_t*)(dh + (size_t)(gr+8)*CH + cc) = h1;
            *(uint32_t*)(dl + (size_t)(gr+8)*CH + cc) = l1;
        }
    }
}

// ================= kernel: flash attention via mma.sync =====================
// grid (8 qtiles, 128 bh), 8 warps x 16 q-rows. 64-key tiles, 3-stage ring,
// one sync per tile. No-max softmax (exp2; scale folded into q upstream).
#define ATT_SMEM 110592
__global__ void __launch_bounds__(256, 2)
attn_mma()
{
    extern __shared__ char sm_[];
    uint32_t sb = smem_u32(sm_);
    int tid = threadIdx.x;
    int w = tid >> 5, l = tid & 31;
    int t = l & 3, g = l >> 2;
    int qt = blockIdx.x, bh = blockIdx.y;
    int b = bh >> 4, h = bh & 15;
    const size_t rowq0 = (size_t)(b*SEQ + qt*128);
    const size_t rowk0 = (size_t)(b*SEQ);
    const int hc = h*HDIM;
    const int wrow = w*16;

#pragma unroll
    for (int i = 0; i < 8; i++) {
        int tk = tid + i*256;
        int hl = tk >> 10, r = (tk >> 3) & 127, c = tk & 7;
        uint32_t dst = sb + hl*18432 + r*144 + c*16;
        const __nv_bfloat16* src = (hl ? g_qlo : g_qhi) + (rowq0 + r)*CH + hc + c*8;
        cp16(dst, src);
    }
    asm volatile("cp.async.commit_group;");
    asm volatile("cp.async.wait_group 0;");
    __syncthreads();
    uint32_t qh[4][4], ql[4][4];
#pragma unroll
    for (int s = 0; s < 4; s++) {
        uint32_t a = sb + (wrow + (l & 15))*144 + s*32 + (l >> 4)*16;
        ldm4(qh[s][0], qh[s][1], qh[s][2], qh[s][3], a);
        ldm4(ql[s][0], ql[s][1], ql[s][2], ql[s][3], a + 18432);
    }
    __syncthreads();

    auto issue_kv = [&](int kt) {
        uint32_t base = sb + (kt % 3)*36864;
        const size_t row = rowk0 + (size_t)kt*64;
#pragma unroll
        for (int i = 0; i < 8; i++) {
            int tk = tid + (i << 8);
            int arr = tk >> 9, r = (tk >> 3) & 63, c = tk & 7;
            uint32_t dst = base + arr*9216 + r*144 + c*16;
            const __nv_bfloat16* src =
                (arr == 0) ? g_khi : (arr == 1) ? g_klo : (arr == 2) ? g_vhi : g_vlo;
            cp16(dst, src + (row + r)*CH + hc + c*8);
        }
        asm volatile("cp.async.commit_group;");
    };

    float o[8][4];
#pragma unroll
    for (int j = 0; j < 8; j++)
#pragma unroll
        for (int e = 0; e < 4; e++) o[j][e] = 0.f;
    float lr0 = 0.f, lr1 = 0.f;

    issue_kv(0);
    issue_kv(1);
    for (int kt = 0; kt < 16; kt++) {
        if (kt < 15) asm volatile("cp.async.wait_group 1;");
        else         asm volatile("cp.async.wait_group 0;");
        __syncthreads();
        if (kt + 2 < 16) issue_kv(kt + 2);
        uint32_t base = sb + (kt % 3)*36864;

        float s[8][4];
#pragma unroll
        for (int j = 0; j < 8; j++)
#pragma unroll
            for (int e = 0; e < 4; e++) s[j][e] = 0.f;
#pragma unroll
        for (int s4 = 0; s4 < 4; s4++) {
            uint32_t kf_hi[8][2], kf_lo[8][2];
#pragma unroll
            for (int jp = 0; jp < 4; jp++) {
                uint32_t a = base + (jp*16 + (l & 7) + ((l >> 4) & 1)*8)*144
                                  + s4*32 + ((l >> 3) & 1)*16;
                ldm4(kf_hi[2*jp][0], kf_hi[2*jp][1], kf_hi[2*jp+1][0], kf_hi[2*jp+1][1], a);
                ldm4(kf_lo[2*jp][0], kf_lo[2*jp][1], kf_lo[2*jp+1][0], kf_lo[2*jp+1][1], a + 9216);
            }
#pragma unroll
            for (int j = 0; j < 8; j++) {
                mma16816(s[j], qh[s4], kf_hi[j]);
                mma16816(s[j], ql[s4], kf_hi[j]);
                mma16816(s[j], qh[s4], kf_lo[j]);
            }
        }

#pragma unroll
        for (int j = 0; j < 8; j++) {
            s[j][0] = ex2(s[j][0]); s[j][1] = ex2(s[j][1]);
            s[j][2] = ex2(s[j][2]); s[j][3] = ex2(s[j][3]);
            lr0 += s[j][0] + s[j][1];
            lr1 += s[j][2] + s[j][3];
        }

        uint32_t vbse = base + 18432;
#pragma unroll
        for (int s4 = 0; s4 < 4; s4++) {
            uint32_t pa_hi[4], pa_lo[4];
            split2(s[2*s4][0],   s[2*s4][1],   pa_hi[0], pa_lo[0]);
            split2(s[2*s4][2],   s[2*s4][3],   pa_hi[1], pa_lo[1]);
            split2(s[2*s4+1][0], s[2*s4+1][1], pa_hi[2], pa_lo[2]);
            split2(s[2*s4+1][2], s[2*s4+1][3], pa_hi[3], pa_lo[3]);
            uint32_t vf_hi[8][2], vf_lo[8][2];
#pragma unroll
            for (int jp = 0; jp < 4; jp++) {
                uint32_t a = vbse + (16*s4 + (l & 15))*144 + jp*32 + (l >> 4)*16;
                ldm4t(vf_hi[2*jp][0], vf_hi[2*jp][1], vf_hi[2*jp+1][0], vf_hi[2*jp+1][1], a);
                ldm4t(vf_lo[2*jp][0], vf_lo[2*jp][1], vf_lo[2*jp+1][0], vf_lo[2*jp+1][1], a + 9216);
            }
#pragma unroll
            for (int j = 0; j < 8; j++) {
                mma16816(o[j], pa_hi, vf_hi[j]);
                mma16816(o[j], pa_lo, vf_hi[j]);
                mma16816(o[j], pa_hi, vf_lo[j]);
            }
        }
    }

    lr0 += __shfl_xor_sync(0xffffffffu, lr0, 1);
    lr0 += __shfl_xor_sync(0xffffffffu, lr0, 2);
    lr1 += __shfl_xor_sync(0xffffffffu, lr1, 1);
    lr1 += __shfl_xor_sync(0xffffffffu, lr1, 2);
    float inv0 = 1.0f / lr0, inv1 = 1.0f / lr1;
    size_t r0 = rowq0 + wrow + g;
#pragma unroll
    for (int j = 0; j < 8; j++) {
        int col = hc + j*8 + 2*t;
        uint32_t h0, l0, h1, l1;
        split2(o[j][0]*inv0, o[j][1]*inv0, h0, l0);
        split2(o[j][2]*inv1, o[j][3]*inv1, h1, l1);
        *(uint32_t*)(g_chi + r0*CH + col)     = h0;
        *(uint32_t*)(g_clo + r0*CH + col)     = l0;
        *(uint32_t*)(g_chi + (r0+8)*CH + col) = h1;
        *(uint32_t*)(g_clo + (r0+8)*CH + col) = l1;
    }
}

// ================= launch ====================================================
extern "C" void kernel_launch(void* const* d_in, const int* in_sizes, int n_in,
                              void* d_out, int out_size)
{
    (void)in_sizes; (void)n_in; (void)out_size;
    const float* x      = (const float*)d_in[0];
    const float* qkv_w  = (const float*)d_in[1];
    const float* qkv_b  = (const float*)d_in[2];
    const float* proj_w = (const float*)d_in[3];
    const float* proj_b = (const float*)d_in[4];
    const float* lqa    = (const float*)d_in[5];
    const float* lqb    = (const float*)d_in[6];
    const float* lva    = (const float*)d_in[7];
    const float* lvb    = (const float*)d_in[8];
    float* out = (float*)d_out;

    cudaFuncSetAttribute(attn_mma, cudaFuncAttributeMaxDynamicSharedMemorySize, ATT_SMEM);
    cudaFuncSetAttribute(wgemm,    cudaFuncAttributeMaxDynamicSharedMemorySize, WG_SMEM);
    cudaFuncSetAttribute(lora_xa2, cudaFuncAttributeMaxDynamicSharedMemorySize, 65536);

    convert_split<<<M_TOT*CH/4/256, 256>>>(x,      M_TOT*CH/4, 0);
    convert_split<<<3*CH*CH/4/256,  256>>>(qkv_w,  3*CH*CH/4,  1);
    convert_split<<<CH*CH/4/256,    256>>>(proj_w, CH*CH/4,    2);
    lora_xa2<<<M_TOT/8, 256, 65536>>>(x, lqa, lva);

    wgemm<<<dim3(3*CH/128, M_TOT/128), 256, WG_SMEM>>>(qkv_b, lqb, lvb, nullptr, 1);
    attn_mma<<<dim3(SEQ/128, BATCH*HEADS), 256, ATT_SMEM>>>();
    wgemm<<<dim3(CH/128, M_TOT/128), 256, WG_SMEM>>>(proj_b, nullptr, nullptr, out, 0);
}

// round 8
// speedup vs baseline: 3.4978x; 1.0060x over previous
#include <cuda_runtime.h>
#include <cuda_bf16.h>
#include <cstdint>
#include <math.h>

#define BATCH 8
#define SEQ   1024
#define CH    1024
#define HEADS 16
#define HDIM  64
#define RANK  8
#define M_TOT (BATCH*SEQ)   // 8192
#define LORA_SCALE 2.0f
#define SCALEQ 0.18033688011112042f   // 0.125 * log2(e), folded into stored q

// ================= scratch (device globals; no runtime allocation) ==========
__device__ float g_xaq[M_TOT*RANK];
__device__ float g_xav[M_TOT*RANK];
__device__ __nv_bfloat16 g_xhi[(size_t)M_TOT*CH];
__device__ __nv_bfloat16 g_xlo[(size_t)M_TOT*CH];
__device__ __nv_bfloat16 g_wqhi[3*CH*CH];
__device__ __nv_bfloat16 g_wqlo[3*CH*CH];
__device__ __nv_bfloat16 g_wphi[CH*CH];
__device__ __nv_bfloat16 g_wplo[CH*CH];
__device__ __nv_bfloat16 g_qhi[(size_t)M_TOT*CH];   // q pre-scaled by SCALEQ
__device__ __nv_bfloat16 g_qlo[(size_t)M_TOT*CH];
__device__ __nv_bfloat16 g_khi[(size_t)M_TOT*CH];
__device__ __nv_bfloat16 g_klo[(size_t)M_TOT*CH];
__device__ __nv_bfloat16 g_vhi[(size_t)M_TOT*CH];
__device__ __nv_bfloat16 g_vlo[(size_t)M_TOT*CH];
__device__ __nv_bfloat16 g_chi[(size_t)M_TOT*CH];
__device__ __nv_bfloat16 g_clo[(size_t)M_TOT*CH];

// ================= small helpers ============================================
__device__ __forceinline__ uint32_t smem_u32(const void* p) {
    uint32_t a;
    asm("{ .reg .u64 t; cvta.to.shared.u64 t, %1; cvt.u32.u64 %0, t; }" : "=r"(a) : "l"(p));
    return a;
}
__device__ __forceinline__ void cp16(uint32_t dst, const void* src) {
    asm volatile("cp.async.cg.shared.global [%0], [%1], 16;" :: "r"(dst), "l"(src));
}
__device__ __forceinline__ void ldm4(uint32_t& r0, uint32_t& r1, uint32_t& r2, uint32_t& r3,
                                     uint32_t addr) {
    asm volatile("ldmatrix.sync.aligned.m8n8.x4.shared.b16 {%0,%1,%2,%3}, [%4];"
                 : "=r"(r0), "=r"(r1), "=r"(r2), "=r"(r3) : "r"(addr));
}
__device__ __forceinline__ void ldm4t(uint32_t& r0, uint32_t& r1, uint32_t& r2, uint32_t& r3,
                                      uint32_t addr) {
    asm volatile("ldmatrix.sync.aligned.m8n8.x4.trans.shared.b16 {%0,%1,%2,%3}, [%4];"
                 : "=r"(r0), "=r"(r1), "=r"(r2), "=r"(r3) : "r"(addr));
}
__device__ __forceinline__ void mma16816(float* c, const uint32_t* a, const uint32_t* b) {
    asm volatile("mma.sync.aligned.m16n8k16.row.col.f32.bf16.bf16.f32 "
                 "{%0,%1,%2,%3}, {%4,%5,%6,%7}, {%8,%9}, {%0,%1,%2,%3};"
                 : "+f"(c[0]), "+f"(c[1]), "+f"(c[2]), "+f"(c[3])
                 : "r"(a[0]), "r"(a[1]), "r"(a[2]), "r"(a[3]), "r"(b[0]), "r"(b[1]));
}
// cheap hi/lo split: hi = truncate-to-bf16 (PRMT), lo = packed-round of residue
__device__ __forceinline__ void split2(float v0, float v1, uint32_t& whi, uint32_t& wlo) {
    uint32_t u0 = __float_as_uint(v0), u1 = __float_as_uint(v1);
    whi = __byte_perm(u0, u1, 0x7632);
    float l0 = v0 - __uint_as_float(u0 & 0xFFFF0000u);
    float l1 = v1 - __uint_as_float(u1 & 0xFFFF0000u);
    asm("cvt.rn.bf16x2.f32 %0, %1, %2;" : "=r"(wlo) : "f"(l1), "f"(l0));
}
__device__ __forceinline__ float ex2(float x) {
    float y; asm("ex2.approx.f32 %0, %1;" : "=f"(y) : "f"(x)); return y;
}

// ================= kernel: fp32 -> (bf16 hi, bf16 lo) split (weights) =======
__global__ __launch_bounds__(256)
void convert_split(const float* __restrict__ src, int n4, int which)
{
    __nv_bfloat16 *hi, *lo;
    if (which == 1) { hi = g_wqhi; lo = g_wqlo; }
    else            { hi = g_wphi; lo = g_wplo; }
    int i = blockIdx.x * 256 + threadIdx.x;
    if (i >= n4) return;
    float4 v = ((const float4*)src)[i];
    uint32_t h0, l0, h1, l1;
    split2(v.x, v.y, h0, l0);
    split2(v.z, v.w, h1, l1);
    *(uint2*)(hi + 4*(size_t)i) = make_uint2(h0, h1);
    *(uint2*)(lo + 4*(size_t)i) = make_uint2(l0, l1);
}

// ================= kernel: fused x hi/lo split + rank-8 LoRA "A" ============
// 8 rows/block. Row lives in registers: one x read feeds BOTH the bf16
// hi/lo split stores AND the LoRA-A reductions (kills the separate
// convert_x pass, 64MB of traffic).
__global__ __launch_bounds__(256)
void prep_x_lora(const float* __restrict__ x,
                 const float* __restrict__ aq,
                 const float* __restrict__ av)
{
    extern __shared__ float As[];   // 16*1024 floats
    int tid = threadIdx.x;
    const float4* aq4 = (const float4*)aq;
    const float4* av4 = (const float4*)av;
    float4* As4 = (float4*)As;
    for (int i = tid; i < 4096; i += 256)
        As4[i] = (i < 2048) ? aq4[i] : av4[i - 2048];
    __syncthreads();

    int w = tid >> 5, l = tid & 31;
    int m = blockIdx.x*8 + w;
    const float4* xr = (const float4*)(x + (size_t)m*CH);
    float4 xv[8];
#pragma unroll
    for (int jj = 0; jj < 8; jj++) xv[jj] = xr[jj*32 + l];

    // hi/lo split stores (coalesced: lane-consecutive uint2)
    uint2* xh2 = (uint2*)(g_xhi + (size_t)m*CH);
    uint2* xl2 = (uint2*)(g_xlo + (size_t)m*CH);
#pragma unroll
    for (int jj = 0; jj < 8; jj++) {
        uint32_t h0, l0, h1, l1;
        split2(xv[jj].x, xv[jj].y, h0, l0);
        split2(xv[jj].z, xv[jj].w, h1, l1);
        xh2[jj*32 + l] = make_uint2(h0, h1);
        xl2[jj*32 + l] = make_uint2(l0, l1);
    }

    // LoRA-A reductions
    float acc[16];
#pragma unroll
    for (int o = 0; o < 16; o++) {
        float s = 0.f;
#pragma unroll
        for (int jj = 0; jj < 8; jj++) {
            float4 a = As4[o*256 + jj*32 + l];
            s += xv[jj].x*a.x + xv[jj].y*a.y + xv[jj].z*a.z + xv[jj].w*a.w;
        }
        acc[o] = s;
    }
#pragma unroll
    for (int o = 0; o < 16; o++)
#pragma unroll
        for (int off = 16; off; off >>= 1)
            acc[o] += __shfl_xor_sync(0xffffffffu, acc[o], off);
    if (l < 8)       g_xaq[m*RANK + l] = acc[l];
    else if (l < 16) g_xav[m*RANK + (l - 8)] = acc[l];
}

// ================= kernel: warp-MMA bf16-split GEMM v4 ======================
// 128x128 CTA tile. K-chunk = 32 original cols; stage row = hi 64B | lo 64B
// | pad 16 -> 144B. 3 split terms are in-register passes. 3-stage ring.
#define NCHK 32     // 1024/32
#define WG_SMEM 110592
__global__ void __launch_bounds__(256, 2)
wgemm(const float* __restrict__ bias,
      const float* __restrict__ lqb, const float* __restrict__ lvb,
      float* __restrict__ outp, int mode)
{
    extern __shared__ char wsm[];
    uint32_t sb = smem_u32(wsm);
    int tid = threadIdx.x;
    int w = tid >> 5, l = tid & 31;
    int t = l & 3, g = l >> 2;
    int wm = w >> 1, wn = w & 1;
    int bm = blockIdx.y, bn = blockIdx.x;
    int am0 = bm*128, bn0 = bn*128;

    const __nv_bfloat16 *Ahi, *Alo, *Bhi, *Blo;
    if (mode == 1) { Ahi = g_xhi; Alo = g_xlo; Bhi = g_wqhi; Blo = g_wqlo; }
    else           { Ahi = g_chi; Alo = g_clo; Bhi = g_wphi; Blo = g_wplo; }

    float acc[2][8][4];
#pragma unroll
    for (int mi = 0; mi < 2; mi++)
#pragma unroll
        for (int ni = 0; ni < 8; ni++)
#pragma unroll
            for (int e = 0; e < 4; e++) acc[mi][ni][e] = 0.f;

    auto issue = [&](int c) {
        int kin = c << 5;
        uint32_t base = sb + (c % 3)*36864;
#pragma unroll
        for (int i = 0; i < 8; i++) {
            int tk = tid + (i << 8);
            int mat = tk >> 10, r = (tk >> 3) & 127, sub = tk & 7;
            uint32_t dst = base + mat*18432 + r*144 + sub*16;
            int cc = (sub & 3) << 3;
            const __nv_bfloat16* src;
            if (mat == 0) src = ((sub & 4) ? Alo : Ahi) + (((size_t)(am0 + r)) << 10) + kin + cc;
            else          src = ((sub & 4) ? Blo : Bhi) + (((size_t)(bn0 + r)) << 10) + kin + cc;
            cp16(dst, src);
        }
        asm volatile("cp.async.commit_group;");
    };

    issue(0);
    issue(1);
    for (int c = 0; c < NCHK; c++) {
        if (c < NCHK-1) asm volatile("cp.async.wait_group 1;");
        else            asm volatile("cp.async.wait_group 0;");
        __syncthreads();
        if (c + 2 < NCHK) issue(c + 2);
        uint32_t Ab = sb + (c % 3)*36864;
        uint32_t Bb = Ab + 18432;
#pragma unroll
        for (int s = 0; s < 2; s++) {
            uint32_t afh[2][4], afl[2][4];
#pragma unroll
            for (int mi = 0; mi < 2; mi++) {
                uint32_t a0 = Ab + (wm*32 + mi*16 + (l & 15))*144 + s*32 + (l >> 4)*16;
                ldm4(afh[mi][0], afh[mi][1], afh[mi][2], afh[mi][3], a0);
                ldm4(afl[mi][0], afl[mi][1], afl[mi][2], afl[mi][3], a0 + 64);
            }
#pragma unroll
            for (int jp = 0; jp < 4; jp++) {
                uint32_t b0 = Bb + (wn*64 + jp*16 + (l & 7) + ((l >> 4) & 1)*8)*144
                                 + s*32 + ((l >> 3) & 1)*16;
                uint32_t bh[4], bl[4];
                ldm4(bh[0], bh[1], bh[2], bh[3], b0);
                ldm4(bl[0], bl[1], bl[2], bl[3], b0 + 64);
#pragma unroll
                for (int mi = 0; mi < 2; mi++) {
                    mma16816(acc[mi][2*jp],   afh[mi], bh);
                    mma16816(acc[mi][2*jp],   afl[mi], bh);
                    mma16816(acc[mi][2*jp],   afh[mi], bl);
                    mma16816(acc[mi][2*jp+1], afh[mi], bh + 2);
                    mma16816(acc[mi][2*jp+1], afl[mi], bh + 2);
                    mma16816(acc[mi][2*jp+1], afh[mi], bl + 2);
                }
            }
        }
    }
    __syncthreads();

    // ---------------- epilogue -------------------------------------------
    if (mode == 0) {
#pragma unroll
        for (int mi = 0; mi < 2; mi++) {
            int gr = am0 + wm*32 + mi*16 + g;
#pragma unroll
            for (int ni = 0; ni < 8; ni++) {
                int col = bn0 + wn*64 + ni*8 + 2*t;
                float b0 = bias[col], b1 = bias[col+1];
                float2 v0 = { acc[mi][ni][0] + b0, acc[mi][ni][1] + b1 };
                float2 v1 = { acc[mi][ni][2] + b0, acc[mi][ni][3] + b1 };
                *(float2*)(outp + (size_t)gr*CH + col)     = v0;
                *(float2*)(outp + (size_t)(gr+8)*CH + col) = v1;
            }
        }
        return;
    }
    int treg = bn >> 3;   // 0:q 1:k 2:v
    __nv_bfloat16 *dh, *dl; int cb;
    if (treg == 0)      { dh = g_qhi; dl = g_qlo; cb = 0;    }
    else if (treg == 1) { dh = g_khi; dl = g_klo; cb = 1024; }
    else                { dh = g_vhi; dl = g_vlo; cb = 2048; }

    float lsum[2][8][4];
#pragma unroll
    for (int mi = 0; mi < 2; mi++)
#pragma unroll
        for (int ni = 0; ni < 8; ni++)
#pragma unroll
            for (int e = 0; e < 4; e++) lsum[mi][ni][e] = 0.f;

    if (treg != 1) {
        const float* lbase = (treg == 0) ? lqb : lvb;
        float* lbs = (float*)wsm;
        *(float4*)&lbs[tid*4] =
            *(const float4*)&lbase[((size_t)(bn0 - cb))*RANK + tid*4];
        __syncthreads();
        const float* xsrc = (treg == 0) ? g_xaq : g_xav;
        float xa_[2][2][8];
#pragma unroll
        for (int mi = 0; mi < 2; mi++)
#pragma unroll
            for (int h = 0; h < 2; h++) {
                int gr = am0 + wm*32 + mi*16 + g + h*8;
                const float4* xp = (const float4*)(xsrc + (size_t)gr*RANK);
                float4 x0 = xp[0], x1 = xp[1];
                xa_[mi][h][0]=x0.x; xa_[mi][h][1]=x0.y; xa_[mi][h][2]=x0.z; xa_[mi][h][3]=x0.w;
                xa_[mi][h][4]=x1.x; xa_[mi][h][5]=x1.y; xa_[mi][h][6]=x1.z; xa_[mi][h][7]=x1.w;
            }
#pragma unroll
        for (int mi = 0; mi < 2; mi++)
#pragma unroll
            for (int ni = 0; ni < 8; ni++) {
                int lcol = wn*64 + ni*8 + 2*t;
                const float* lb0 = lbs + lcol*RANK;
                const float* lb1 = lbs + (lcol+1)*RANK;
                float s00=0.f, s01=0.f, s10=0.f, s11=0.f;
#pragma unroll
                for (int r = 0; r < 8; r++) {
                    s00 += xa_[mi][0][r]*lb0[r];
                    s01 += xa_[mi][0][r]*lb1[r];
                    s10 += xa_[mi][1][r]*lb0[r];
                    s11 += xa_[mi][1][r]*lb1[r];
                }
                lsum[mi][ni][0] = LORA_SCALE*s00; lsum[mi][ni][1] = LORA_SCALE*s01;
                lsum[mi][ni][2] = LORA_SCALE*s10; lsum[mi][ni][3] = LORA_SCALE*s11;
            }
    }
    float qsc = (treg == 0) ? SCALEQ : 1.0f;
#pragma unroll
    for (int mi = 0; mi < 2; mi++) {
        int gr = am0 + wm*32 + mi*16 + g;
#pragma unroll
        for (int ni = 0; ni < 8; ni++) {
            int col = bn0 + wn*64 + ni*8 + 2*t;
            float b0 = bias[col], b1 = bias[col+1];
            float v00 = (acc[mi][ni][0] + b0 + lsum[mi][ni][0]) * qsc;
            float v01 = (acc[mi][ni][1] + b1 + lsum[mi][ni][1]) * qsc;
            float v10 = (acc[mi][ni][2] + b0 + lsum[mi][ni][2]) * qsc;
            float v11 = (acc[mi][ni][3] + b1 + lsum[mi][ni][3]) * qsc;
            uint32_t h0, l0, h1, l1;
            split2(v00, v01, h0, l0);
            split2(v10, v11, h1, l1);
            int cc = col - cb;
            *(uint32_t*)(dh + (size_t)gr*CH + cc)     = h0;
            *(uint32_t*)(dl + (size_t)gr*CH + cc)     = l0;
            *(uint32_t*)(dh + (size_t)(gr+8)*CH + cc) = h1;
            *(uint32_t*)(dl + (size_t)(gr+8)*CH + cc) = l1;
        }
    }
}

// ================= kernel: flash attention via mma.sync =====================
// grid (8 qtiles, 128 bh), 8 warps x 16 q-rows. 64-key tiles, 3-stage ring,
// one sync per tile. No-max softmax (exp2; scale folded into q upstream).
#define ATT_SMEM 110592
__global__ void __launch_bounds__(256, 2)
attn_mma()
{
    extern __shared__ char sm_[];
    uint32_t sb = smem_u32(sm_);
    int tid = threadIdx.x;
    int w = tid >> 5, l = tid & 31;
    int t = l & 3, g = l >> 2;
    int qt = blockIdx.x, bh = blockIdx.y;
    int b = bh >> 4, h = bh & 15;
    const size_t rowq0 = (size_t)(b*SEQ + qt*128);
    const size_t rowk0 = (size_t)(b*SEQ);
    const int hc = h*HDIM;
    const int wrow = w*16;

#pragma unroll
    for (int i = 0; i < 8; i++) {
        int tk = tid + i*256;
        int hl = tk >> 10, r = (tk >> 3) & 127, c = tk & 7;
        uint32_t dst = sb + hl*18432 + r*144 + c*16;
        const __nv_bfloat16* src = (hl ? g_qlo : g_qhi) + (rowq0 + r)*CH + hc + c*8;
        cp16(dst, src);
    }
    asm volatile("cp.async.commit_group;");
    asm volatile("cp.async.wait_group 0;");
    __syncthreads();
    uint32_t qh[4][4], ql[4][4];
#pragma unroll
    for (int s = 0; s < 4; s++) {
        uint32_t a = sb + (wrow + (l & 15))*144 + s*32 + (l >> 4)*16;
        ldm4(qh[s][0], qh[s][1], qh[s][2], qh[s][3], a);
        ldm4(ql[s][0], ql[s][1], ql[s][2], ql[s][3], a + 18432);
    }
    __syncthreads();

    auto issue_kv = [&](int kt) {
        uint32_t base = sb + (kt % 3)*36864;
        const size_t row = rowk0 + (size_t)kt*64;
#pragma unroll
        for (int i = 0; i < 8; i++) {
            int tk = tid + (i << 8);
            int arr = tk >> 9, r = (tk >> 3) & 63, c = tk & 7;
            uint32_t dst = base + arr*9216 + r*144 + c*16;
            const __nv_bfloat16* src =
                (arr == 0) ? g_khi : (arr == 1) ? g_klo : (arr == 2) ? g_vhi : g_vlo;
            cp16(dst, src + (row + r)*CH + hc + c*8);
        }
        asm volatile("cp.async.commit_group;");
    };

    float o[8][4];
#pragma unroll
    for (int j = 0; j < 8; j++)
#pragma unroll
        for (int e = 0; e < 4; e++) o[j][e] = 0.f;
    float lr0 = 0.f, lr1 = 0.f;

    issue_kv(0);
    issue_kv(1);
    for (int kt = 0; kt < 16; kt++) {
        if (kt < 15) asm volatile("cp.async.wait_group 1;");
        else         asm volatile("cp.async.wait_group 0;");
        __syncthreads();
        if (kt + 2 < 16) issue_kv(kt + 2);
        uint32_t base = sb + (kt % 3)*36864;

        float s[8][4];
#pragma unroll
        for (int j = 0; j < 8; j++)
#pragma unroll
            for (int e = 0; e < 4; e++) s[j][e] = 0.f;
#pragma unroll
        for (int s4 = 0; s4 < 4; s4++) {
            uint32_t kf_hi[8][2], kf_lo[8][2];
#pragma unroll
            for (int jp = 0; jp < 4; jp++) {
                uint32_t a = base + (jp*16 + (l & 7) + ((l >> 4) & 1)*8)*144
                                  + s4*32 + ((l >> 3) & 1)*16;
                ldm4(kf_hi[2*jp][0], kf_hi[2*jp][1], kf_hi[2*jp+1][0], kf_hi[2*jp+1][1], a);
                ldm4(kf_lo[2*jp][0], kf_lo[2*jp][1], kf_lo[2*jp+1][0], kf_lo[2*jp+1][1], a + 9216);
            }
#pragma unroll
            for (int j = 0; j < 8; j++) {
                mma16816(s[j], qh[s4], kf_hi[j]);
                mma16816(s[j], ql[s4], kf_hi[j]);
                mma16816(s[j], qh[s4], kf_lo[j]);
            }
        }

#pragma unroll
        for (int j = 0; j < 8; j++) {
            s[j][0] = ex2(s[j][0]); s[j][1] = ex2(s[j][1]);
            s[j][2] = ex2(s[j][2]); s[j][3] = ex2(s[j][3]);
            lr0 += s[j][0] + s[j][1];
            lr1 += s[j][2] + s[j][3];
        }

        uint32_t vbse = base + 18432;
#pragma unroll
        for (int s4 = 0; s4 < 4; s4++) {
            uint32_t pa_hi[4], pa_lo[4];
            split2(s[2*s4][0],   s[2*s4][1],   pa_hi[0], pa_lo[0]);
            split2(s[2*s4][2],   s[2*s4][3],   pa_hi[1], pa_lo[1]);
            split2(s[2*s4+1][0], s[2*s4+1][1], pa_hi[2], pa_lo[2]);
            split2(s[2*s4+1][2], s[2*s4+1][3], pa_hi[3], pa_lo[3]);
            uint32_t vf_hi[8][2], vf_lo[8][2];
#pragma unroll
            for (int jp = 0; jp < 4; jp++) {
                uint32_t a = vbse + (16*s4 + (l & 15))*144 + jp*32 + (l >> 4)*16;
                ldm4t(vf_hi[2*jp][0], vf_hi[2*jp][1], vf_hi[2*jp+1][0], vf_hi[2*jp+1][1], a);
                ldm4t(vf_lo[2*jp][0], vf_lo[2*jp][1], vf_lo[2*jp+1][0], vf_lo[2*jp+1][1], a + 9216);
            }
#pragma unroll
            for (int j = 0; j < 8; j++) {
                mma16816(o[j], pa_hi, vf_hi[j]);
                mma16816(o[j], pa_lo, vf_hi[j]);
                mma16816(o[j], pa_hi, vf_lo[j]);
            }
        }
    }

    lr0 += __shfl_xor_sync(0xffffffffu, lr0, 1);
    lr0 += __shfl_xor_sync(0xffffffffu, lr0, 2);
    lr1 += __shfl_xor_sync(0xffffffffu, lr1, 1);
    lr1 += __shfl_xor_sync(0xffffffffu, lr1, 2);
    float inv0 = 1.0f / lr0, inv1 = 1.0f / lr1;
    size_t r0 = rowq0 + wrow + g;
#pragma unroll
    for (int j = 0; j < 8; j++) {
        int col = hc + j*8 + 2*t;
        uint32_t h0, l0, h1, l1;
        split2(o[j][0]*inv0, o[j][1]*inv0, h0, l0);
        split2(o[j][2]*inv1, o[j][3]*inv1, h1, l1);
        *(uint32_t*)(g_chi + r0*CH + col)     = h0;
        *(uint32_t*)(g_clo + r0*CH + col)     = l0;
        *(uint32_t*)(g_chi + (r0+8)*CH + col) = h1;
        *(uint32_t*)(g_clo + (r0+8)*CH + col) = l1;
    }
}

// ================= launch ====================================================
extern "C" void kernel_launch(void* const* d_in, const int* in_sizes, int n_in,
                              void* d_out, int out_size)
{
    (void)in_sizes; (void)n_in; (void)out_size;
    const float* x      = (const float*)d_in[0];
    const float* qkv_w  = (const float*)d_in[1];
    const float* qkv_b  = (const float*)d_in[2];
    const float* proj_w = (const float*)d_in[3];
    const float* proj_b = (const float*)d_in[4];
    const float* lqa    = (const float*)d_in[5];
    const float* lqb    = (const float*)d_in[6];
    const float* lva    = (const float*)d_in[7];
    const float* lvb    = (const float*)d_in[8];
    float* out = (float*)d_out;

    cudaFuncSetAttribute(attn_mma,    cudaFuncAttributeMaxDynamicSharedMemorySize, ATT_SMEM);
    cudaFuncSetAttribute(wgemm,       cudaFuncAttributeMaxDynamicSharedMemorySize, WG_SMEM);
    cudaFuncSetAttribute(prep_x_lora, cudaFuncAttributeMaxDynamicSharedMemorySize, 65536);

    // launch order chosen so index 3 (the profiled slot) = wgemm QKV
    prep_x_lora<<<M_TOT/8, 256, 65536>>>(x, lqa, lva);                     // 0
    convert_split<<<3*CH*CH/4/256, 256>>>(qkv_w,  3*CH*CH/4, 1);           // 1
    convert_split<<<CH*CH/4/256,   256>>>(proj_w, CH*CH/4,   2);           // 2
    wgemm<<<dim3(3*CH/128, M_TOT/128), 256, WG_SMEM>>>(qkv_b, lqb, lvb, nullptr, 1);  // 3
    attn_mma<<<dim3(SEQ/128, BATCH*HEADS), 256, ATT_SMEM>>>();             // 4
    wgemm<<<dim3(CH/128, M_TOT/128), 256, WG_SMEM>>>(proj_b, nullptr, nullptr, out, 0); // 5
}